// round 13
// baseline (speedup 1.0000x reference)
#include <cuda_runtime.h>
#include <cuda_bf16.h>
#include <math.h>
#include <stdint.h>

#define TSEQ 2048
#define CDIM 2048
#define QKVD 3072
#define NHEAD 32
#define HSZ 64

// scratch (no allocations allowed) — all bf16 hi/lo pairs
__device__ __nv_bfloat16 g_qh[TSEQ * QKVD];   // qkv hi
__device__ __nv_bfloat16 g_ql[TSEQ * QKVD];   // qkv lo
__device__ __nv_bfloat16 g_xh[TSEQ * CDIM];   // x hi
__device__ __nv_bfloat16 g_xl[TSEQ * CDIM];   // x lo
__device__ __nv_bfloat16 g_wah[QKVD * CDIM];  // W_attn hi
__device__ __nv_bfloat16 g_wal[QKVD * CDIM];  // W_attn lo
__device__ __nv_bfloat16 g_wph[CDIM * CDIM];  // W_proj hi
__device__ __nv_bfloat16 g_wpl[CDIM * CDIM];  // W_proj lo
__device__ __nv_bfloat16 g_yh[TSEQ * CDIM];   // attn out hi
__device__ __nv_bfloat16 g_yl[TSEQ * CDIM];   // attn out lo

// ---------------------------------------------------------------------------
// helpers
// ---------------------------------------------------------------------------
__device__ __forceinline__ uint32_t smem_u32(const void* p) {
    uint32_t a;
    asm("{ .reg .u64 t; cvta.to.shared.u64 t, %1; cvt.u32.u64 %0, t; }"
        : "=r"(a) : "l"(p));
    return a;
}

__device__ __forceinline__ void ldmatrix_x4(uint32_t& r0, uint32_t& r1,
                                            uint32_t& r2, uint32_t& r3,
                                            uint32_t addr) {
    asm volatile("ldmatrix.sync.aligned.m8n8.x4.shared.b16 {%0,%1,%2,%3}, [%4];"
                 : "=r"(r0), "=r"(r1), "=r"(r2), "=r"(r3) : "r"(addr));
}

__device__ __forceinline__ void ldmatrix_x4_t(uint32_t& r0, uint32_t& r1,
                                              uint32_t& r2, uint32_t& r3,
                                              uint32_t addr) {
    asm volatile("ldmatrix.sync.aligned.m8n8.x4.trans.shared.b16 {%0,%1,%2,%3}, [%4];"
                 : "=r"(r0), "=r"(r1), "=r"(r2), "=r"(r3) : "r"(addr));
}

__device__ __forceinline__ void mma16816(float* c, const uint32_t* a,
                                         uint32_t b0, uint32_t b1) {
    asm volatile(
        "mma.sync.aligned.m16n8k16.row.col.f32.bf16.bf16.f32 "
        "{%0,%1,%2,%3}, {%4,%5,%6,%7}, {%8,%9}, {%0,%1,%2,%3};"
        : "+f"(c[0]), "+f"(c[1]), "+f"(c[2]), "+f"(c[3])
        : "r"(a[0]), "r"(a[1]), "r"(a[2]), "r"(a[3]), "r"(b0), "r"(b1));
}

__device__ __forceinline__ void cp16(uint32_t dst, const void* src) {
    asm volatile("cp.async.cg.shared.global [%0], [%1], 16;"
                 :: "r"(dst), "l"(src) : "memory");
}
__device__ __forceinline__ void cp_commit() {
    asm volatile("cp.async.commit_group;" ::: "memory");
}
template<int N> __device__ __forceinline__ void cp_wait() {
    asm volatile("cp.async.wait_group %0;" :: "n"(N) : "memory");
}

#define SWZ(o)   ((o) ^ (((o) >> 3) & 0x70))

// fp32 pair -> packed bf16 hi + bf16 lo (residual)
__device__ __forceinline__ void pack_hl(float x, float y, uint32_t& h, uint32_t& l) {
    __nv_bfloat162 hh = __floats2bfloat162_rn(x, y);
    float2 f = __bfloat1622float2(hh);
    __nv_bfloat162 ll = __floats2bfloat162_rn(x - f.x, y - f.y);
    h = *reinterpret_cast<uint32_t*>(&hh);
    l = *reinterpret_cast<uint32_t*>(&ll);
}

__device__ __forceinline__ float2 unpack_hl(uint32_t h, uint32_t l) {
    __nv_bfloat162 hh = *reinterpret_cast<__nv_bfloat162*>(&h);
    __nv_bfloat162 ll = *reinterpret_cast<__nv_bfloat162*>(&l);
    float2 a = __bfloat1622float2(hh);
    float2 b = __bfloat1622float2(ll);
    return make_float2(a.x + b.x, a.y + b.y);
}

// ---------------------------------------------------------------------------
// fp32 -> bf16 hi/lo split converter
// ---------------------------------------------------------------------------
__global__ void __launch_bounds__(256)
cvt_hl(const float* __restrict__ src, __nv_bfloat16* __restrict__ h,
       __nv_bfloat16* __restrict__ l, int npairs)
{
    const int i = blockIdx.x * 256 + threadIdx.x;
    if (i >= npairs) return;
    float2 v = ((const float2*)src)[i];
    uint32_t hh, ll;
    pack_hl(v.x, v.y, hh, ll);
    ((uint32_t*)h)[i] = hh;
    ((uint32_t*)l)[i] = ll;
}

// ---------------------------------------------------------------------------
// bf16 hi/lo NT GEMM: C[M,N] = A[M,K]*B[N,K]^T + bias[N]   (bf16x3 products)
// 128x128 tile, BK=64, 256 threads (2x4 warps, warp tile 64x32),
// 3-stage cp.async pipeline (64KB/stage). MMAs ordered product-major so
// consecutive MMAs hit different accumulators (RAW distance 4).
// ---------------------------------------------------------------------------
static constexpr int GSTAGE = 65536;
static constexpr int GEMM_SMEM_BYTES = 1024 + 3 * GSTAGE;   // 197632

__device__ __forceinline__ void gemm_issue(
    uint32_t stg, const __nv_bfloat16* a0, const __nv_bfloat16* a1,
    const __nv_bfloat16* b0, const __nv_bfloat16* b1, int KDIM, int tid)
{
    const __nv_bfloat16* base[4] = {a0, a1, b0, b1};
#pragma unroll
    for (int t4 = 0; t4 < 4; ++t4) {
        const uint32_t tb = stg + t4 * 16384;
        const __nv_bfloat16* src = base[t4];
#pragma unroll
        for (int it = 0; it < 4; ++it) {
            const int idx = it * 256 + tid;
            const int row = idx >> 3, ch = idx & 7;
            cp16(tb + SWZ((uint32_t)(row * 128 + ch * 16)),
                 src + (size_t)row * KDIM + ch * 8);
        }
    }
}

template<int NDIM, int KDIM, bool OUT_HL>
__global__ void __launch_bounds__(256, 1)
gemm_bf16(const __nv_bfloat16* __restrict__ Ah, const __nv_bfloat16* __restrict__ Al,
          const __nv_bfloat16* __restrict__ Bh, const __nv_bfloat16* __restrict__ Bl,
          const float* __restrict__ bias, float* __restrict__ C,
          __nv_bfloat16* __restrict__ Ch, __nv_bfloat16* __restrict__ Cl)
{
    extern __shared__ char smem_raw[];
    const uint32_t sb = (smem_u32(smem_raw) + 1023u) & ~1023u;

    const int tid  = threadIdx.x;
    const int wid  = tid >> 5;
    const int lane = tid & 31;
    const int m0 = blockIdx.y * 128;
    const int n0 = blockIdx.x * 128;
    const int wm = (wid >> 2) * 64;
    const int wn = (wid & 3) * 32;

    const __nv_bfloat16* A0 = Ah + (size_t)m0 * KDIM;
    const __nv_bfloat16* A1 = Al + (size_t)m0 * KDIM;
    const __nv_bfloat16* B0 = Bh + (size_t)n0 * KDIM;
    const __nv_bfloat16* B1 = Bl + (size_t)n0 * KDIM;

    float acc[4][4][4];
#pragma unroll
    for (int i = 0; i < 4; ++i)
#pragma unroll
        for (int j = 0; j < 4; ++j)
#pragma unroll
            for (int r = 0; r < 4; ++r) acc[i][j][r] = 0.f;

    const int lrow16 = lane & 15;
    const int khalfB = (lane >> 4) * 16;
    const int ITERS = KDIM / 64;

    gemm_issue(sb,              A0,       A1,       B0,       B1,       KDIM, tid); cp_commit();
    gemm_issue(sb + GSTAGE,     A0 + 64,  A1 + 64,  B0 + 64,  B1 + 64,  KDIM, tid); cp_commit();
    gemm_issue(sb + 2 * GSTAGE, A0 + 128, A1 + 128, B0 + 128, B1 + 128, KDIM, tid); cp_commit();

    for (int kt = 0; kt < ITERS; ++kt) {
        const int sidx = kt % 3;
        const uint32_t stg = sb + sidx * GSTAGE;
        cp_wait<2>();
        __syncthreads();

#pragma unroll
        for (int s = 0; s < 4; ++s) {
            const uint32_t kb = (uint32_t)(s * 32 + khalfB);
            uint32_t bh[2][4], bl[2][4];
#pragma unroll
            for (int nj2 = 0; nj2 < 2; ++nj2) {
                const uint32_t roff = SWZ((uint32_t)((wn + nj2 * 16 + lrow16) * 128) + kb);
                ldmatrix_x4(bh[nj2][0], bh[nj2][1], bh[nj2][2], bh[nj2][3],
                            stg + 32768 + roff);
                ldmatrix_x4(bl[nj2][0], bl[nj2][1], bl[nj2][2], bl[nj2][3],
                            stg + 49152 + roff);
            }
#pragma unroll
            for (int mi = 0; mi < 4; ++mi) {
                const uint32_t aoff = SWZ((uint32_t)((wm + mi * 16 + lrow16) * 128) + kb);
                uint32_t ah[4], al[4];
                ldmatrix_x4(ah[0], ah[1], ah[2], ah[3], stg + aoff);
                ldmatrix_x4(al[0], al[1], al[2], al[3], stg + 16384 + aoff);
                // product-major: same-acc RAW distance = 4 MMAs
#pragma unroll
                for (int nj = 0; nj < 4; ++nj)
                    mma16816(acc[mi][nj], ah,
                             bh[nj >> 1][nj & 1], bh[nj >> 1][(nj & 1) + 2]);
#pragma unroll
                for (int nj = 0; nj < 4; ++nj)
                    mma16816(acc[mi][nj], ah,
                             bl[nj >> 1][nj & 1], bl[nj >> 1][(nj & 1) + 2]);
#pragma unroll
                for (int nj = 0; nj < 4; ++nj)
                    mma16816(acc[mi][nj], al,
                             bh[nj >> 1][nj & 1], bh[nj >> 1][(nj & 1) + 2]);
            }
        }

        __syncthreads();
        if (kt + 3 < ITERS) {
            const int ko = (kt + 3) * 64;
            gemm_issue(stg, A0 + ko, A1 + ko, B0 + ko, B1 + ko, KDIM, tid);
        }
        cp_commit();
    }

    // epilogue
    const int qrow = lane >> 2;
    const int qcol = (lane & 3) * 2;
#pragma unroll
    for (int mi = 0; mi < 4; ++mi) {
        const int r0 = m0 + wm + mi * 16 + qrow;
#pragma unroll
        for (int nj = 0; nj < 4; ++nj) {
            const int c0 = n0 + wn + nj * 8 + qcol;
            const float bx = bias[c0], by = bias[c0 + 1];
            const float v00 = acc[mi][nj][0] + bx, v01 = acc[mi][nj][1] + by;
            const float v10 = acc[mi][nj][2] + bx, v11 = acc[mi][nj][3] + by;
            if (OUT_HL) {
                uint32_t h, l;
                pack_hl(v00, v01, h, l);
                *(uint32_t*)(Ch + (size_t)r0 * NDIM + c0) = h;
                *(uint32_t*)(Cl + (size_t)r0 * NDIM + c0) = l;
                pack_hl(v10, v11, h, l);
                *(uint32_t*)(Ch + (size_t)(r0 + 8) * NDIM + c0) = h;
                *(uint32_t*)(Cl + (size_t)(r0 + 8) * NDIM + c0) = l;
            } else {
                *(float2*)&C[(size_t)r0 * NDIM + c0]       = make_float2(v00, v01);
                *(float2*)&C[(size_t)(r0 + 8) * NDIM + c0] = make_float2(v10, v11);
            }
        }
    }
}

// ---------------------------------------------------------------------------
// RoPE in-place on qkv hi/lo. One warp per (token, rope-slot).
// ---------------------------------------------------------------------------
__global__ void __launch_bounds__(256)
rope_hl(__nv_bfloat16* __restrict__ qh, __nv_bfloat16* __restrict__ ql,
        const float* __restrict__ cosb, const float* __restrict__ sinb)
{
    const int gid  = blockIdx.x * 8 + (threadIdx.x >> 5);
    const int lane = threadIdx.x & 31;
    const int t   = gid / 40;
    const int s40 = gid % 40;
    const int ss  = s40 % 5;             // 0-3 q, 4 k
    const int slot = (s40 / 5) * 6 + ss;
    const int d = 2 * lane;

    const size_t off = (size_t)t * QKVD + slot * 64 + d;
    uint32_t h = *(const uint32_t*)(qh + off);
    uint32_t l = *(const uint32_t*)(ql + off);
    float2 v = unpack_hl(h, l);

    float px = __shfl_xor_sync(0xffffffffu, v.x, 4);
    float py = __shfl_xor_sync(0xffffffffu, v.y, 4);
    if (d < 16) {
        const float rx = (d < 8) ? -px : px;
        const float ry = (d < 8) ? -py : py;
        const float c0 = cosb[t * 16 + d],     s0 = sinb[t * 16 + d];
        const float c1 = cosb[t * 16 + d + 1], s1 = sinb[t * 16 + d + 1];
        v.x = v.x * c0 + rx * s0;
        v.y = v.y * c1 + ry * s1;
    }
    if (ss < 4) { v.x *= 0.125f; v.y *= 0.125f; }

    pack_hl(v.x, v.y, h, l);
    *(uint32_t*)(qh + off) = h;
    *(uint32_t*)(ql + off) = l;
}

// ---------------------------------------------------------------------------
// Flash attention, causal, mma.sync bf16x3, output bf16 hi/lo.
// MMAs interleaved across the two accumulators per pair (RAW distance 2).
// ---------------------------------------------------------------------------
static constexpr int FL_STAGE = 65536;
static constexpr int FLASH_SMEM_BYTES = 1024 + 32768 + 2 * FL_STAGE;

__device__ __forceinline__ void flash_issue_kv(
    uint32_t SB, const __nv_bfloat16* qh, const __nv_bfloat16* ql,
    int n0, int koff, int voff, int tid)
{
#pragma unroll
    for (int p = 0; p < 4; ++p) {
        const int idx = p * 256 + tid;
        const int row = idx >> 3, ch = idx & 7;
        const uint32_t off = SWZ((uint32_t)(row * 128 + ch * 16));
        const size_t gk = (size_t)(n0 + row) * QKVD + koff + ch * 8;
        const size_t gv = (size_t)(n0 + row) * QKVD + voff + ch * 8;
        cp16(SB + off,         qh + gk);
        cp16(SB + 16384 + off, ql + gk);
        cp16(SB + 32768 + off, qh + gv);
        cp16(SB + 49152 + off, ql + gv);
    }
}

__global__ void __launch_bounds__(256, 1)
flash_mma(const __nv_bfloat16* __restrict__ qh,
          const __nv_bfloat16* __restrict__ ql,
          __nv_bfloat16* __restrict__ yh, __nv_bfloat16* __restrict__ yl)
{
    extern __shared__ char smem_raw[];
    const uint32_t sb = (smem_u32(smem_raw) + 1023u) & ~1023u;

    const int tid  = threadIdx.x;
    const int wid  = tid >> 5;
    const int lane = tid & 31;
    const int h  = blockIdx.x;
    const int m0 = (15 - (int)blockIdx.y) * 128;
    const int nb = m0 / 128 + 1;
    const int g = h >> 2;
    const int qoff = g * 384 + (h & 3) * 64;
    const int koff = g * 384 + 256;
    const int voff = g * 384 + 320;
    const int wm = wid * 16;

#pragma unroll
    for (int p = 0; p < 4; ++p) {
        const int idx = p * 256 + tid;
        const int row = idx >> 3, ch = idx & 7;
        const uint32_t off = SWZ((uint32_t)(row * 128 + ch * 16));
        const size_t gq = (size_t)(m0 + row) * QKVD + qoff + ch * 8;
        cp16(sb + off,         qh + gq);
        cp16(sb + 16384 + off, ql + gq);
    }
    flash_issue_kv(sb + 32768, qh, ql, 0, koff, voff, tid);
    cp_commit();
    if (nb > 1) {
        flash_issue_kv(sb + 32768 + FL_STAGE, qh, ql, 128, koff, voff, tid);
        cp_commit();
        cp_wait<1>();
    } else {
        cp_wait<0>();
    }
    __syncthreads();

    uint32_t qfh[4][4], qfl[4][4];
#pragma unroll
    for (int s = 0; s < 4; ++s) {
        const uint32_t aoff = SWZ((uint32_t)((wm + (lane & 15)) * 128
                                             + s * 32 + (lane >> 4) * 16));
        ldmatrix_x4(qfh[s][0], qfh[s][1], qfh[s][2], qfh[s][3], sb + aoff);
        ldmatrix_x4(qfl[s][0], qfl[s][1], qfl[s][2], qfl[s][3], sb + 16384 + aoff);
    }

    float O[8][4];
#pragma unroll
    for (int nj = 0; nj < 8; ++nj)
#pragma unroll
        for (int r = 0; r < 4; ++r) O[nj][r] = 0.f;
    float m_0 = -1e30f, m_1 = -1e30f, l_0 = 0.f, l_1 = 0.f;

    for (int kt = 0; kt < nb; ++kt) {
        const uint32_t SB = sb + 32768 + (kt & 1) * FL_STAGE;
        const uint32_t VB = SB + 32768;

        float S[16][4];
#pragma unroll
        for (int nf = 0; nf < 16; ++nf)
#pragma unroll
            for (int r = 0; r < 4; ++r) S[nf][r] = 0.f;

#pragma unroll
        for (int s = 0; s < 4; ++s) {
            const uint32_t kb = (uint32_t)(s * 32 + (lane >> 4) * 16);
#pragma unroll
            for (int njp = 0; njp < 8; ++njp) {
                const uint32_t roff = SWZ((uint32_t)((njp * 16 + (lane & 15)) * 128) + kb);
                uint32_t kh[4], kl[4];
                ldmatrix_x4(kh[0], kh[1], kh[2], kh[3], SB + roff);
                ldmatrix_x4(kl[0], kl[1], kl[2], kl[3], SB + 16384 + roff);
                // product-major, acc-interleaved (RAW distance 2)
                mma16816(S[2 * njp],     qfh[s], kh[0], kh[2]);
                mma16816(S[2 * njp + 1], qfh[s], kh[1], kh[3]);
                mma16816(S[2 * njp],     qfh[s], kl[0], kl[2]);
                mma16816(S[2 * njp + 1], qfh[s], kl[1], kl[3]);
                mma16816(S[2 * njp],     qfl[s], kh[0], kh[2]);
                mma16816(S[2 * njp + 1], qfl[s], kh[1], kh[3]);
            }
        }

        if (kt == nb - 1) {
            const int bc = 2 * (lane & 3);
            const int lim0 = wm + (lane >> 2);
            const int lim1 = lim0 + 8;
#pragma unroll
            for (int nf = 0; nf < 16; ++nf) {
                const int c0 = nf * 8 + bc;
                if (c0 > lim0)     S[nf][0] = -1e30f;
                if (c0 + 1 > lim0) S[nf][1] = -1e30f;
                if (c0 > lim1)     S[nf][2] = -1e30f;
                if (c0 + 1 > lim1) S[nf][3] = -1e30f;
            }
        }

        float mx0 = -1e30f, mx1 = -1e30f;
#pragma unroll
        for (int nf = 0; nf < 16; ++nf) {
            mx0 = fmaxf(mx0, fmaxf(S[nf][0], S[nf][1]));
            mx1 = fmaxf(mx1, fmaxf(S[nf][2], S[nf][3]));
        }
        mx0 = fmaxf(mx0, __shfl_xor_sync(0xffffffffu, mx0, 1));
        mx0 = fmaxf(mx0, __shfl_xor_sync(0xffffffffu, mx0, 2));
        mx1 = fmaxf(mx1, __shfl_xor_sync(0xffffffffu, mx1, 1));
        mx1 = fmaxf(mx1, __shfl_xor_sync(0xffffffffu, mx1, 2));
        const float mn0 = fmaxf(m_0, mx0), mn1 = fmaxf(m_1, mx1);
        const float f0 = __expf(m_0 - mn0), f1 = __expf(m_1 - mn1);
        m_0 = mn0; m_1 = mn1;

        float rs0 = 0.f, rs1 = 0.f;
#pragma unroll
        for (int nf = 0; nf < 16; ++nf) {
            S[nf][0] = __expf(S[nf][0] - mn0);
            S[nf][1] = __expf(S[nf][1] - mn0);
            S[nf][2] = __expf(S[nf][2] - mn1);
            S[nf][3] = __expf(S[nf][3] - mn1);
            rs0 += S[nf][0] + S[nf][1];
            rs1 += S[nf][2] + S[nf][3];
        }
        rs0 += __shfl_xor_sync(0xffffffffu, rs0, 1);
        rs0 += __shfl_xor_sync(0xffffffffu, rs0, 2);
        rs1 += __shfl_xor_sync(0xffffffffu, rs1, 1);
        rs1 += __shfl_xor_sync(0xffffffffu, rs1, 2);
        l_0 = l_0 * f0 + rs0;
        l_1 = l_1 * f1 + rs1;
#pragma unroll
        for (int nj = 0; nj < 8; ++nj) {
            O[nj][0] *= f0; O[nj][1] *= f0;
            O[nj][2] *= f1; O[nj][3] *= f1;
        }

        const uint32_t kr   = (uint32_t)(((lane & 8) ? 8 : 0) + (lane & 7));
        const uint32_t dsel = (lane & 16) ? 8u : 0u;
#pragma unroll
        for (int t = 0; t < 8; ++t) {
            uint32_t ph[4], pl[4];
            pack_hl(S[2 * t][0],     S[2 * t][1],     ph[0], pl[0]);
            pack_hl(S[2 * t][2],     S[2 * t][3],     ph[1], pl[1]);
            pack_hl(S[2 * t + 1][0], S[2 * t + 1][1], ph[2], pl[2]);
            pack_hl(S[2 * t + 1][2], S[2 * t + 1][3], ph[3], pl[3]);
#pragma unroll
            for (int db = 0; db < 64; db += 16) {
                const uint32_t voff2 = SWZ((uint32_t)((t * 16 + kr) * 128
                                                      + (db + dsel) * 2));
                uint32_t vh[4], vl[4];
                ldmatrix_x4_t(vh[0], vh[1], vh[2], vh[3], VB + voff2);
                ldmatrix_x4_t(vl[0], vl[1], vl[2], vl[3], VB + 16384 + voff2);
                const int oj = db / 8;
                // product-major, acc-interleaved (RAW distance 2)
                mma16816(O[oj],     ph, vh[0], vh[1]);
                mma16816(O[oj + 1], ph, vh[2], vh[3]);
                mma16816(O[oj],     ph, vl[0], vl[1]);
                mma16816(O[oj + 1], ph, vl[2], vl[3]);
                mma16816(O[oj],     pl, vh[0], vh[1]);
                mma16816(O[oj + 1], pl, vh[2], vh[3]);
            }
        }

        __syncthreads();
        if (kt + 1 < nb) {
            if (kt + 2 < nb) {
                flash_issue_kv(sb + 32768 + (kt & 1) * FL_STAGE, qh, ql,
                               (kt + 2) * 128, koff, voff, tid);
                cp_commit();
                cp_wait<1>();
            } else {
                cp_wait<0>();
            }
            __syncthreads();
        }
    }

    const float inv0 = 1.f / l_0, inv1 = 1.f / l_1;
    const int r0 = m0 + wm + (lane >> 2);
    const int col0 = h * 64 + 2 * (lane & 3);
#pragma unroll
    for (int nj = 0; nj < 8; ++nj) {
        const int col = col0 + nj * 8;
        uint32_t hh, ll;
        pack_hl(O[nj][0] * inv0, O[nj][1] * inv0, hh, ll);
        *(uint32_t*)(yh + (size_t)r0 * CDIM + col) = hh;
        *(uint32_t*)(yl + (size_t)r0 * CDIM + col) = ll;
        pack_hl(O[nj][2] * inv1, O[nj][3] * inv1, hh, ll);
        *(uint32_t*)(yh + (size_t)(r0 + 8) * CDIM + col) = hh;
        *(uint32_t*)(yl + (size_t)(r0 + 8) * CDIM + col) = ll;
    }
}

// ---------------------------------------------------------------------------
extern "C" void kernel_launch(void* const* d_in, const int* in_sizes, int n_in,
                              void* d_out, int out_size)
{
    const float* x      = (const float*)d_in[0];
    const float* cosb   = (const float*)d_in[1];
    const float* sinb   = (const float*)d_in[2];
    const float* W_attn = (const float*)d_in[3];
    const float* b_attn = (const float*)d_in[4];
    const float* W_proj = (const float*)d_in[5];
    const float* b_proj = (const float*)d_in[6];
    float* out = (float*)d_out;

    __nv_bfloat16 *qh, *ql, *xh, *xl, *wah, *wal, *wph, *wpl, *yh, *yl;
    cudaGetSymbolAddress((void**)&qh,  g_qh);
    cudaGetSymbolAddress((void**)&ql,  g_ql);
    cudaGetSymbolAddress((void**)&xh,  g_xh);
    cudaGetSymbolAddress((void**)&xl,  g_xl);
    cudaGetSymbolAddress((void**)&wah, g_wah);
    cudaGetSymbolAddress((void**)&wal, g_wal);
    cudaGetSymbolAddress((void**)&wph, g_wph);
    cudaGetSymbolAddress((void**)&wpl, g_wpl);
    cudaGetSymbolAddress((void**)&yh,  g_yh);
    cudaGetSymbolAddress((void**)&yl,  g_yl);

    cudaFuncSetAttribute(gemm_bf16<QKVD, CDIM, true>,
                         cudaFuncAttributeMaxDynamicSharedMemorySize, GEMM_SMEM_BYTES);
    cudaFuncSetAttribute(gemm_bf16<CDIM, CDIM, false>,
                         cudaFuncAttributeMaxDynamicSharedMemorySize, GEMM_SMEM_BYTES);
    cudaFuncSetAttribute(flash_mma,
                         cudaFuncAttributeMaxDynamicSharedMemorySize, FLASH_SMEM_BYTES);

    // 0) split inputs to bf16 hi/lo
    cvt_hl<<<(TSEQ * CDIM / 2 + 255) / 256, 256>>>(x, xh, xl, TSEQ * CDIM / 2);
    cvt_hl<<<(QKVD * CDIM / 2 + 255) / 256, 256>>>(W_attn, wah, wal, QKVD * CDIM / 2);
    cvt_hl<<<(CDIM * CDIM / 2 + 255) / 256, 256>>>(W_proj, wph, wpl, CDIM * CDIM / 2);

    // 1) QKV GEMM + bias -> hi/lo qkv
    gemm_bf16<QKVD, CDIM, true>
        <<<dim3(QKVD / 128, TSEQ / 128), 256, GEMM_SMEM_BYTES>>>(
            xh, xl, wah, wal, b_attn, nullptr, qh, ql);

    // 2) RoPE in place on hi/lo (scale folded into Q)
    rope_hl<<<TSEQ * 40 / 8, 256>>>(qh, ql, cosb, sinb);

    // 3) causal flash attention -> hi/lo y
    flash_mma<<<dim3(NHEAD, TSEQ / 128), 256, FLASH_SMEM_BYTES>>>(qh, ql, yh, yl);

    // 4) output projection + bias -> fp32 out
    gemm_bf16<CDIM, CDIM, false>
        <<<dim3(CDIM / 128, TSEQ / 128), 256, GEMM_SMEM_BYTES>>>(
            yh, yl, wph, wpl, b_proj, out, nullptr, nullptr);
}

// round 14
// speedup vs baseline: 1.2533x; 1.2533x over previous
#include <cuda_runtime.h>
#include <cuda_bf16.h>
#include <cuda_fp16.h>
#include <math.h>
#include <stdint.h>

#define TSEQ 2048
#define CDIM 2048
#define QKVD 3072
#define NHEAD 32
#define HSZ 64

// scratch (no allocations allowed)
__device__ __nv_bfloat16 g_qh[TSEQ * QKVD];   // qkv hi (bf16, for flash)
__device__ __nv_bfloat16 g_ql[TSEQ * QKVD];   // qkv lo (bf16, for flash)
__device__ __half g_xh[TSEQ * CDIM];          // x hi (fp16)
__device__ __half g_xl[TSEQ * CDIM];          // x lo (fp16)
__device__ __half g_wa[QKVD * CDIM];          // W_attn (fp16 single)
__device__ __half g_wp[CDIM * CDIM];          // W_proj (fp16 single)
__device__ __half g_yh[TSEQ * CDIM];          // attn out hi (fp16)
__device__ __half g_yl[TSEQ * CDIM];          // attn out lo (fp16)

// ---------------------------------------------------------------------------
// helpers
// ---------------------------------------------------------------------------
__device__ __forceinline__ uint32_t smem_u32(const void* p) {
    uint32_t a;
    asm("{ .reg .u64 t; cvta.to.shared.u64 t, %1; cvt.u32.u64 %0, t; }"
        : "=r"(a) : "l"(p));
    return a;
}

__device__ __forceinline__ void ldmatrix_x4(uint32_t& r0, uint32_t& r1,
                                            uint32_t& r2, uint32_t& r3,
                                            uint32_t addr) {
    asm volatile("ldmatrix.sync.aligned.m8n8.x4.shared.b16 {%0,%1,%2,%3}, [%4];"
                 : "=r"(r0), "=r"(r1), "=r"(r2), "=r"(r3) : "r"(addr));
}

__device__ __forceinline__ void ldmatrix_x4_t(uint32_t& r0, uint32_t& r1,
                                              uint32_t& r2, uint32_t& r3,
                                              uint32_t addr) {
    asm volatile("ldmatrix.sync.aligned.m8n8.x4.trans.shared.b16 {%0,%1,%2,%3}, [%4];"
                 : "=r"(r0), "=r"(r1), "=r"(r2), "=r"(r3) : "r"(addr));
}

// bf16 mma (flash)
__device__ __forceinline__ void mma16816(float* c, const uint32_t* a,
                                         uint32_t b0, uint32_t b1) {
    asm volatile(
        "mma.sync.aligned.m16n8k16.row.col.f32.bf16.bf16.f32 "
        "{%0,%1,%2,%3}, {%4,%5,%6,%7}, {%8,%9}, {%0,%1,%2,%3};"
        : "+f"(c[0]), "+f"(c[1]), "+f"(c[2]), "+f"(c[3])
        : "r"(a[0]), "r"(a[1]), "r"(a[2]), "r"(a[3]), "r"(b0), "r"(b1));
}

// fp16 mma (GEMMs)
__device__ __forceinline__ void mma16816f(float* c, const uint32_t* a,
                                          uint32_t b0, uint32_t b1) {
    asm volatile(
        "mma.sync.aligned.m16n8k16.row.col.f32.f16.f16.f32 "
        "{%0,%1,%2,%3}, {%4,%5,%6,%7}, {%8,%9}, {%0,%1,%2,%3};"
        : "+f"(c[0]), "+f"(c[1]), "+f"(c[2]), "+f"(c[3])
        : "r"(a[0]), "r"(a[1]), "r"(a[2]), "r"(a[3]), "r"(b0), "r"(b1));
}

__device__ __forceinline__ void cp16(uint32_t dst, const void* src) {
    asm volatile("cp.async.cg.shared.global [%0], [%1], 16;"
                 :: "r"(dst), "l"(src) : "memory");
}
__device__ __forceinline__ void cp_commit() {
    asm volatile("cp.async.commit_group;" ::: "memory");
}
template<int N> __device__ __forceinline__ void cp_wait() {
    asm volatile("cp.async.wait_group %0;" :: "n"(N) : "memory");
}

#define SWZ(o)   ((o) ^ (((o) >> 3) & 0x70))

// fp32 pair -> packed bf16 hi + bf16 lo (residual)
__device__ __forceinline__ void pack_hl(float x, float y, uint32_t& h, uint32_t& l) {
    __nv_bfloat162 hh = __floats2bfloat162_rn(x, y);
    float2 f = __bfloat1622float2(hh);
    __nv_bfloat162 ll = __floats2bfloat162_rn(x - f.x, y - f.y);
    h = *reinterpret_cast<uint32_t*>(&hh);
    l = *reinterpret_cast<uint32_t*>(&ll);
}

// fp32 pair -> packed fp16 hi + fp16 lo (residual)
__device__ __forceinline__ void pack_hl16(float x, float y, uint32_t& h, uint32_t& l) {
    __half2 hh = __floats2half2_rn(x, y);
    float2 f = __half22float2(hh);
    __half2 ll = __floats2half2_rn(x - f.x, y - f.y);
    h = *reinterpret_cast<uint32_t*>(&hh);
    l = *reinterpret_cast<uint32_t*>(&ll);
}

__device__ __forceinline__ float2 unpack_hl(uint32_t h, uint32_t l) {
    __nv_bfloat162 hh = *reinterpret_cast<__nv_bfloat162*>(&h);
    __nv_bfloat162 ll = *reinterpret_cast<__nv_bfloat162*>(&l);
    float2 a = __bfloat1622float2(hh);
    float2 b = __bfloat1622float2(ll);
    return make_float2(a.x + b.x, a.y + b.y);
}

// ---------------------------------------------------------------------------
// converters
// ---------------------------------------------------------------------------
__global__ void __launch_bounds__(256)
cvt_hl16(const float* __restrict__ src, __half* __restrict__ h,
         __half* __restrict__ l, int npairs)
{
    const int i = blockIdx.x * 256 + threadIdx.x;
    if (i >= npairs) return;
    float2 v = ((const float2*)src)[i];
    uint32_t hh, ll;
    pack_hl16(v.x, v.y, hh, ll);
    ((uint32_t*)h)[i] = hh;
    ((uint32_t*)l)[i] = ll;
}

__global__ void __launch_bounds__(256)
cvt_16(const float* __restrict__ src, __half* __restrict__ w, int npairs)
{
    const int i = blockIdx.x * 256 + threadIdx.x;
    if (i >= npairs) return;
    float2 v = ((const float2*)src)[i];
    __half2 w2 = __floats2half2_rn(v.x, v.y);
    ((uint32_t*)w)[i] = *reinterpret_cast<uint32_t*>(&w2);
}

// ---------------------------------------------------------------------------
// fp16x2 NT GEMM: C[M,N] = (Ah+Al)[M,K] * B[N,K]^T + bias[N]  (2 products)
// 128x128 tile, BK=64, 256 threads (2x4 warps, warp tile 64x32),
// 3-stage cp.async pipeline (48KB/stage: Ah 16K, Al 16K, B 16K).
// OUT_HL: write bf16 hi/lo (qkv) else fp32.
// ---------------------------------------------------------------------------
static constexpr int GSTAGE = 49152;
static constexpr int GEMM_SMEM_BYTES = 1024 + 3 * GSTAGE;   // 148480

__device__ __forceinline__ void gemm_issue(
    uint32_t stg, const __half* a0, const __half* a1,
    const __half* b0, int KDIM, int tid)
{
    const __half* base[3] = {a0, a1, b0};
#pragma unroll
    for (int t4 = 0; t4 < 3; ++t4) {
        const uint32_t tb = stg + t4 * 16384;
        const __half* src = base[t4];
#pragma unroll
        for (int it = 0; it < 4; ++it) {
            const int idx = it * 256 + tid;
            const int row = idx >> 3, ch = idx & 7;
            cp16(tb + SWZ((uint32_t)(row * 128 + ch * 16)),
                 src + (size_t)row * KDIM + ch * 8);
        }
    }
}

template<int NDIM, int KDIM, bool OUT_HL>
__global__ void __launch_bounds__(256, 1)
gemm_f16(const __half* __restrict__ Ah, const __half* __restrict__ Al,
         const __half* __restrict__ B16,
         const float* __restrict__ bias, float* __restrict__ C,
         __nv_bfloat16* __restrict__ Ch, __nv_bfloat16* __restrict__ Cl)
{
    extern __shared__ char smem_raw[];
    const uint32_t sb = (smem_u32(smem_raw) + 1023u) & ~1023u;

    const int tid  = threadIdx.x;
    const int wid  = tid >> 5;
    const int lane = tid & 31;
    const int m0 = blockIdx.y * 128;
    const int n0 = blockIdx.x * 128;
    const int wm = (wid >> 2) * 64;
    const int wn = (wid & 3) * 32;

    const __half* A0 = Ah  + (size_t)m0 * KDIM;
    const __half* A1 = Al  + (size_t)m0 * KDIM;
    const __half* B0 = B16 + (size_t)n0 * KDIM;

    float acc[4][4][4];
#pragma unroll
    for (int i = 0; i < 4; ++i)
#pragma unroll
        for (int j = 0; j < 4; ++j)
#pragma unroll
            for (int r = 0; r < 4; ++r) acc[i][j][r] = 0.f;

    const int lrow16 = lane & 15;
    const int khalfB = (lane >> 4) * 16;
    const int ITERS = KDIM / 64;

    gemm_issue(sb,              A0,       A1,       B0,       KDIM, tid); cp_commit();
    gemm_issue(sb + GSTAGE,     A0 + 64,  A1 + 64,  B0 + 64,  KDIM, tid); cp_commit();
    gemm_issue(sb + 2 * GSTAGE, A0 + 128, A1 + 128, B0 + 128, KDIM, tid); cp_commit();

    for (int kt = 0; kt < ITERS; ++kt) {
        const int sidx = kt % 3;
        const uint32_t stg = sb + sidx * GSTAGE;
        cp_wait<2>();
        __syncthreads();

#pragma unroll
        for (int s = 0; s < 4; ++s) {
            const uint32_t kb = (uint32_t)(s * 32 + khalfB);
            uint32_t bh[2][4];
#pragma unroll
            for (int nj2 = 0; nj2 < 2; ++nj2) {
                const uint32_t roff = SWZ((uint32_t)((wn + nj2 * 16 + lrow16) * 128) + kb);
                ldmatrix_x4(bh[nj2][0], bh[nj2][1], bh[nj2][2], bh[nj2][3],
                            stg + 32768 + roff);
            }
#pragma unroll
            for (int mi = 0; mi < 4; ++mi) {
                const uint32_t aoff = SWZ((uint32_t)((wm + mi * 16 + lrow16) * 128) + kb);
                uint32_t ah[4], al[4];
                ldmatrix_x4(ah[0], ah[1], ah[2], ah[3], stg + aoff);
                ldmatrix_x4(al[0], al[1], al[2], al[3], stg + 16384 + aoff);
                // product-major: same-acc RAW distance = 4 MMAs
#pragma unroll
                for (int nj = 0; nj < 4; ++nj)
                    mma16816f(acc[mi][nj], ah,
                              bh[nj >> 1][nj & 1], bh[nj >> 1][(nj & 1) + 2]);
#pragma unroll
                for (int nj = 0; nj < 4; ++nj)
                    mma16816f(acc[mi][nj], al,
                              bh[nj >> 1][nj & 1], bh[nj >> 1][(nj & 1) + 2]);
            }
        }

        __syncthreads();
        if (kt + 3 < ITERS) {
            const int ko = (kt + 3) * 64;
            gemm_issue(stg, A0 + ko, A1 + ko, B0 + ko, KDIM, tid);
        }
        cp_commit();
    }

    // epilogue
    const int qrow = lane >> 2;
    const int qcol = (lane & 3) * 2;
#pragma unroll
    for (int mi = 0; mi < 4; ++mi) {
        const int r0 = m0 + wm + mi * 16 + qrow;
#pragma unroll
        for (int nj = 0; nj < 4; ++nj) {
            const int c0 = n0 + wn + nj * 8 + qcol;
            const float bx = bias[c0], by = bias[c0 + 1];
            const float v00 = acc[mi][nj][0] + bx, v01 = acc[mi][nj][1] + by;
            const float v10 = acc[mi][nj][2] + bx, v11 = acc[mi][nj][3] + by;
            if (OUT_HL) {
                uint32_t h, l;
                pack_hl(v00, v01, h, l);
                *(uint32_t*)(Ch + (size_t)r0 * NDIM + c0) = h;
                *(uint32_t*)(Cl + (size_t)r0 * NDIM + c0) = l;
                pack_hl(v10, v11, h, l);
                *(uint32_t*)(Ch + (size_t)(r0 + 8) * NDIM + c0) = h;
                *(uint32_t*)(Cl + (size_t)(r0 + 8) * NDIM + c0) = l;
            } else {
                *(float2*)&C[(size_t)r0 * NDIM + c0]       = make_float2(v00, v01);
                *(float2*)&C[(size_t)(r0 + 8) * NDIM + c0] = make_float2(v10, v11);
            }
        }
    }
}

// ---------------------------------------------------------------------------
// RoPE in-place on qkv hi/lo (bf16). One warp per (token, rope-slot).
// ---------------------------------------------------------------------------
__global__ void __launch_bounds__(256)
rope_hl(__nv_bfloat16* __restrict__ qh, __nv_bfloat16* __restrict__ ql,
        const float* __restrict__ cosb, const float* __restrict__ sinb)
{
    const int gid  = blockIdx.x * 8 + (threadIdx.x >> 5);
    const int lane = threadIdx.x & 31;
    const int t   = gid / 40;
    const int s40 = gid % 40;
    const int ss  = s40 % 5;             // 0-3 q, 4 k
    const int slot = (s40 / 5) * 6 + ss;
    const int d = 2 * lane;

    const size_t off = (size_t)t * QKVD + slot * 64 + d;
    uint32_t h = *(const uint32_t*)(qh + off);
    uint32_t l = *(const uint32_t*)(ql + off);
    float2 v = unpack_hl(h, l);

    float px = __shfl_xor_sync(0xffffffffu, v.x, 4);
    float py = __shfl_xor_sync(0xffffffffu, v.y, 4);
    if (d < 16) {
        const float rx = (d < 8) ? -px : px;
        const float ry = (d < 8) ? -py : py;
        const float c0 = cosb[t * 16 + d],     s0 = sinb[t * 16 + d];
        const float c1 = cosb[t * 16 + d + 1], s1 = sinb[t * 16 + d + 1];
        v.x = v.x * c0 + rx * s0;
        v.y = v.y * c1 + ry * s1;
    }
    if (ss < 4) { v.x *= 0.125f; v.y *= 0.125f; }

    pack_hl(v.x, v.y, h, l);
    *(uint32_t*)(qh + off) = h;
    *(uint32_t*)(ql + off) = l;
}

// ---------------------------------------------------------------------------
// Flash attention, causal, mma.sync bf16x3, output fp16 hi/lo.
// ---------------------------------------------------------------------------
static constexpr int FL_STAGE = 65536;
static constexpr int FLASH_SMEM_BYTES = 1024 + 32768 + 2 * FL_STAGE;

__device__ __forceinline__ void flash_issue_kv(
    uint32_t SB, const __nv_bfloat16* qh, const __nv_bfloat16* ql,
    int n0, int koff, int voff, int tid)
{
#pragma unroll
    for (int p = 0; p < 4; ++p) {
        const int idx = p * 256 + tid;
        const int row = idx >> 3, ch = idx & 7;
        const uint32_t off = SWZ((uint32_t)(row * 128 + ch * 16));
        const size_t gk = (size_t)(n0 + row) * QKVD + koff + ch * 8;
        const size_t gv = (size_t)(n0 + row) * QKVD + voff + ch * 8;
        cp16(SB + off,         qh + gk);
        cp16(SB + 16384 + off, ql + gk);
        cp16(SB + 32768 + off, qh + gv);
        cp16(SB + 49152 + off, ql + gv);
    }
}

__global__ void __launch_bounds__(256, 1)
flash_mma(const __nv_bfloat16* __restrict__ qh,
          const __nv_bfloat16* __restrict__ ql,
          __half* __restrict__ yh, __half* __restrict__ yl)
{
    extern __shared__ char smem_raw[];
    const uint32_t sb = (smem_u32(smem_raw) + 1023u) & ~1023u;

    const int tid  = threadIdx.x;
    const int wid  = tid >> 5;
    const int lane = tid & 31;
    const int h  = blockIdx.x;
    const int m0 = (15 - (int)blockIdx.y) * 128;
    const int nb = m0 / 128 + 1;
    const int g = h >> 2;
    const int qoff = g * 384 + (h & 3) * 64;
    const int koff = g * 384 + 256;
    const int voff = g * 384 + 320;
    const int wm = wid * 16;

#pragma unroll
    for (int p = 0; p < 4; ++p) {
        const int idx = p * 256 + tid;
        const int row = idx >> 3, ch = idx & 7;
        const uint32_t off = SWZ((uint32_t)(row * 128 + ch * 16));
        const size_t gq = (size_t)(m0 + row) * QKVD + qoff + ch * 8;
        cp16(sb + off,         qh + gq);
        cp16(sb + 16384 + off, ql + gq);
    }
    flash_issue_kv(sb + 32768, qh, ql, 0, koff, voff, tid);
    cp_commit();
    if (nb > 1) {
        flash_issue_kv(sb + 32768 + FL_STAGE, qh, ql, 128, koff, voff, tid);
        cp_commit();
        cp_wait<1>();
    } else {
        cp_wait<0>();
    }
    __syncthreads();

    uint32_t qfh[4][4], qfl[4][4];
#pragma unroll
    for (int s = 0; s < 4; ++s) {
        const uint32_t aoff = SWZ((uint32_t)((wm + (lane & 15)) * 128
                                             + s * 32 + (lane >> 4) * 16));
        ldmatrix_x4(qfh[s][0], qfh[s][1], qfh[s][2], qfh[s][3], sb + aoff);
        ldmatrix_x4(qfl[s][0], qfl[s][1], qfl[s][2], qfl[s][3], sb + 16384 + aoff);
    }

    float O[8][4];
#pragma unroll
    for (int nj = 0; nj < 8; ++nj)
#pragma unroll
        for (int r = 0; r < 4; ++r) O[nj][r] = 0.f;
    float m_0 = -1e30f, m_1 = -1e30f, l_0 = 0.f, l_1 = 0.f;

    for (int kt = 0; kt < nb; ++kt) {
        const uint32_t SB = sb + 32768 + (kt & 1) * FL_STAGE;
        const uint32_t VB = SB + 32768;

        float S[16][4];
#pragma unroll
        for (int nf = 0; nf < 16; ++nf)
#pragma unroll
            for (int r = 0; r < 4; ++r) S[nf][r] = 0.f;

#pragma unroll
        for (int s = 0; s < 4; ++s) {
            const uint32_t kb = (uint32_t)(s * 32 + (lane >> 4) * 16);
#pragma unroll
            for (int njp = 0; njp < 8; ++njp) {
                const uint32_t roff = SWZ((uint32_t)((njp * 16 + (lane & 15)) * 128) + kb);
                uint32_t kh[4], kl[4];
                ldmatrix_x4(kh[0], kh[1], kh[2], kh[3], SB + roff);
                ldmatrix_x4(kl[0], kl[1], kl[2], kl[3], SB + 16384 + roff);
                mma16816(S[2 * njp],     qfh[s], kh[0], kh[2]);
                mma16816(S[2 * njp + 1], qfh[s], kh[1], kh[3]);
                mma16816(S[2 * njp],     qfh[s], kl[0], kl[2]);
                mma16816(S[2 * njp + 1], qfh[s], kl[1], kl[3]);
                mma16816(S[2 * njp],     qfl[s], kh[0], kh[2]);
                mma16816(S[2 * njp + 1], qfl[s], kh[1], kh[3]);
            }
        }

        if (kt == nb - 1) {
            const int bc = 2 * (lane & 3);
            const int lim0 = wm + (lane >> 2);
            const int lim1 = lim0 + 8;
#pragma unroll
            for (int nf = 0; nf < 16; ++nf) {
                const int c0 = nf * 8 + bc;
                if (c0 > lim0)     S[nf][0] = -1e30f;
                if (c0 + 1 > lim0) S[nf][1] = -1e30f;
                if (c0 > lim1)     S[nf][2] = -1e30f;
                if (c0 + 1 > lim1) S[nf][3] = -1e30f;
            }
        }

        float mx0 = -1e30f, mx1 = -1e30f;
#pragma unroll
        for (int nf = 0; nf < 16; ++nf) {
            mx0 = fmaxf(mx0, fmaxf(S[nf][0], S[nf][1]));
            mx1 = fmaxf(mx1, fmaxf(S[nf][2], S[nf][3]));
        }
        mx0 = fmaxf(mx0, __shfl_xor_sync(0xffffffffu, mx0, 1));
        mx0 = fmaxf(mx0, __shfl_xor_sync(0xffffffffu, mx0, 2));
        mx1 = fmaxf(mx1, __shfl_xor_sync(0xffffffffu, mx1, 1));
        mx1 = fmaxf(mx1, __shfl_xor_sync(0xffffffffu, mx1, 2));
        const float mn0 = fmaxf(m_0, mx0), mn1 = fmaxf(m_1, mx1);
        const float f0 = __expf(m_0 - mn0), f1 = __expf(m_1 - mn1);
        m_0 = mn0; m_1 = mn1;

        float rs0 = 0.f, rs1 = 0.f;
#pragma unroll
        for (int nf = 0; nf < 16; ++nf) {
            S[nf][0] = __expf(S[nf][0] - mn0);
            S[nf][1] = __expf(S[nf][1] - mn0);
            S[nf][2] = __expf(S[nf][2] - mn1);
            S[nf][3] = __expf(S[nf][3] - mn1);
            rs0 += S[nf][0] + S[nf][1];
            rs1 += S[nf][2] + S[nf][3];
        }
        rs0 += __shfl_xor_sync(0xffffffffu, rs0, 1);
        rs0 += __shfl_xor_sync(0xffffffffu, rs0, 2);
        rs1 += __shfl_xor_sync(0xffffffffu, rs1, 1);
        rs1 += __shfl_xor_sync(0xffffffffu, rs1, 2);
        l_0 = l_0 * f0 + rs0;
        l_1 = l_1 * f1 + rs1;
#pragma unroll
        for (int nj = 0; nj < 8; ++nj) {
            O[nj][0] *= f0; O[nj][1] *= f0;
            O[nj][2] *= f1; O[nj][3] *= f1;
        }

        const uint32_t kr   = (uint32_t)(((lane & 8) ? 8 : 0) + (lane & 7));
        const uint32_t dsel = (lane & 16) ? 8u : 0u;
#pragma unroll
        for (int t = 0; t < 8; ++t) {
            uint32_t ph[4], pl[4];
            pack_hl(S[2 * t][0],     S[2 * t][1],     ph[0], pl[0]);
            pack_hl(S[2 * t][2],     S[2 * t][3],     ph[1], pl[1]);
            pack_hl(S[2 * t + 1][0], S[2 * t + 1][1], ph[2], pl[2]);
            pack_hl(S[2 * t + 1][2], S[2 * t + 1][3], ph[3], pl[3]);
#pragma unroll
            for (int db = 0; db < 64; db += 16) {
                const uint32_t voff2 = SWZ((uint32_t)((t * 16 + kr) * 128
                                                      + (db + dsel) * 2));
                uint32_t vh[4], vl[4];
                ldmatrix_x4_t(vh[0], vh[1], vh[2], vh[3], VB + voff2);
                ldmatrix_x4_t(vl[0], vl[1], vl[2], vl[3], VB + 16384 + voff2);
                const int oj = db / 8;
                mma16816(O[oj],     ph, vh[0], vh[1]);
                mma16816(O[oj + 1], ph, vh[2], vh[3]);
                mma16816(O[oj],     ph, vl[0], vl[1]);
                mma16816(O[oj + 1], ph, vl[2], vl[3]);
                mma16816(O[oj],     pl, vh[0], vh[1]);
                mma16816(O[oj + 1], pl, vh[2], vh[3]);
            }
        }

        __syncthreads();
        if (kt + 1 < nb) {
            if (kt + 2 < nb) {
                flash_issue_kv(sb + 32768 + (kt & 1) * FL_STAGE, qh, ql,
                               (kt + 2) * 128, koff, voff, tid);
                cp_commit();
                cp_wait<1>();
            } else {
                cp_wait<0>();
            }
            __syncthreads();
        }
    }

    const float inv0 = 1.f / l_0, inv1 = 1.f / l_1;
    const int r0 = m0 + wm + (lane >> 2);
    const int col0 = h * 64 + 2 * (lane & 3);
#pragma unroll
    for (int nj = 0; nj < 8; ++nj) {
        const int col = col0 + nj * 8;
        uint32_t hh, ll;
        pack_hl16(O[nj][0] * inv0, O[nj][1] * inv0, hh, ll);
        *(uint32_t*)(yh + (size_t)r0 * CDIM + col) = hh;
        *(uint32_t*)(yl + (size_t)r0 * CDIM + col) = ll;
        pack_hl16(O[nj][2] * inv1, O[nj][3] * inv1, hh, ll);
        *(uint32_t*)(yh + (size_t)(r0 + 8) * CDIM + col) = hh;
        *(uint32_t*)(yl + (size_t)(r0 + 8) * CDIM + col) = ll;
    }
}

// ---------------------------------------------------------------------------
extern "C" void kernel_launch(void* const* d_in, const int* in_sizes, int n_in,
                              void* d_out, int out_size)
{
    const float* x      = (const float*)d_in[0];
    const float* cosb   = (const float*)d_in[1];
    const float* sinb   = (const float*)d_in[2];
    const float* W_attn = (const float*)d_in[3];
    const float* b_attn = (const float*)d_in[4];
    const float* W_proj = (const float*)d_in[5];
    const float* b_proj = (const float*)d_in[6];
    float* out = (float*)d_out;

    __nv_bfloat16 *qh, *ql;
    __half *xh, *xl, *wa, *wp, *yh, *yl;
    cudaGetSymbolAddress((void**)&qh, g_qh);
    cudaGetSymbolAddress((void**)&ql, g_ql);
    cudaGetSymbolAddress((void**)&xh, g_xh);
    cudaGetSymbolAddress((void**)&xl, g_xl);
    cudaGetSymbolAddress((void**)&wa, g_wa);
    cudaGetSymbolAddress((void**)&wp, g_wp);
    cudaGetSymbolAddress((void**)&yh, g_yh);
    cudaGetSymbolAddress((void**)&yl, g_yl);

    cudaFuncSetAttribute(gemm_f16<QKVD, CDIM, true>,
                         cudaFuncAttributeMaxDynamicSharedMemorySize, GEMM_SMEM_BYTES);
    cudaFuncSetAttribute(gemm_f16<CDIM, CDIM, false>,
                         cudaFuncAttributeMaxDynamicSharedMemorySize, GEMM_SMEM_BYTES);
    cudaFuncSetAttribute(flash_mma,
                         cudaFuncAttributeMaxDynamicSharedMemorySize, FLASH_SMEM_BYTES);

    // 0) converts: x -> fp16 hi/lo; weights -> fp16 single
    cvt_hl16<<<(TSEQ * CDIM / 2 + 255) / 256, 256>>>(x, xh, xl, TSEQ * CDIM / 2);
    cvt_16<<<(QKVD * CDIM / 2 + 255) / 256, 256>>>(W_attn, wa, QKVD * CDIM / 2);
    cvt_16<<<(CDIM * CDIM / 2 + 255) / 256, 256>>>(W_proj, wp, CDIM * CDIM / 2);

    // 1) QKV GEMM + bias -> bf16 hi/lo qkv (fp16x2 compute)
    gemm_f16<QKVD, CDIM, true>
        <<<dim3(QKVD / 128, TSEQ / 128), 256, GEMM_SMEM_BYTES>>>(
            xh, xl, wa, b_attn, nullptr, qh, ql);

    // 2) RoPE in place on bf16 hi/lo (scale folded into Q)
    rope_hl<<<TSEQ * 40 / 8, 256>>>(qh, ql, cosb, sinb);

    // 3) causal flash attention (bf16x3) -> fp16 hi/lo y
    flash_mma<<<dim3(NHEAD, TSEQ / 128), 256, FLASH_SMEM_BYTES>>>(qh, ql, yh, yl);

    // 4) output projection + bias -> fp32 out (fp16x2 compute)
    gemm_f16<CDIM, CDIM, false>
        <<<dim3(CDIM / 128, TSEQ / 128), 256, GEMM_SMEM_BYTES>>>(
            yh, yl, wp, b_proj, out, nullptr, nullptr);
}

// round 15
// speedup vs baseline: 1.3940x; 1.1122x over previous
#include <cuda_runtime.h>
#include <cuda_bf16.h>
#include <cuda_fp16.h>
#include <math.h>
#include <stdint.h>

#define TSEQ 2048
#define CDIM 2048
#define QKVD 3072
#define NHEAD 32
#define HSZ 64

// scratch (no allocations allowed) — all fp16
__device__ __half g_qh[TSEQ * QKVD];   // qkv hi
__device__ __half g_ql[TSEQ * QKVD];   // qkv lo
__device__ __half g_xh[TSEQ * CDIM];   // x hi
__device__ __half g_xl[TSEQ * CDIM];   // x lo
__device__ __half g_wa[QKVD * CDIM];   // W_attn (single)
__device__ __half g_wp[CDIM * CDIM];   // W_proj (single)
__device__ __half g_yh[TSEQ * CDIM];   // attn out hi
__device__ __half g_yl[TSEQ * CDIM];   // attn out lo

// ---------------------------------------------------------------------------
// helpers
// ---------------------------------------------------------------------------
__device__ __forceinline__ uint32_t smem_u32(const void* p) {
    uint32_t a;
    asm("{ .reg .u64 t; cvta.to.shared.u64 t, %1; cvt.u32.u64 %0, t; }"
        : "=r"(a) : "l"(p));
    return a;
}

__device__ __forceinline__ void ldmatrix_x4(uint32_t& r0, uint32_t& r1,
                                            uint32_t& r2, uint32_t& r3,
                                            uint32_t addr) {
    asm volatile("ldmatrix.sync.aligned.m8n8.x4.shared.b16 {%0,%1,%2,%3}, [%4];"
                 : "=r"(r0), "=r"(r1), "=r"(r2), "=r"(r3) : "r"(addr));
}

__device__ __forceinline__ void ldmatrix_x4_t(uint32_t& r0, uint32_t& r1,
                                              uint32_t& r2, uint32_t& r3,
                                              uint32_t addr) {
    asm volatile("ldmatrix.sync.aligned.m8n8.x4.trans.shared.b16 {%0,%1,%2,%3}, [%4];"
                 : "=r"(r0), "=r"(r1), "=r"(r2), "=r"(r3) : "r"(addr));
}

// fp16 mma
__device__ __forceinline__ void mma16816f(float* c, const uint32_t* a,
                                          uint32_t b0, uint32_t b1) {
    asm volatile(
        "mma.sync.aligned.m16n8k16.row.col.f32.f16.f16.f32 "
        "{%0,%1,%2,%3}, {%4,%5,%6,%7}, {%8,%9}, {%0,%1,%2,%3};"
        : "+f"(c[0]), "+f"(c[1]), "+f"(c[2]), "+f"(c[3])
        : "r"(a[0]), "r"(a[1]), "r"(a[2]), "r"(a[3]), "r"(b0), "r"(b1));
}

__device__ __forceinline__ void cp16(uint32_t dst, const void* src) {
    asm volatile("cp.async.cg.shared.global [%0], [%1], 16;"
                 :: "r"(dst), "l"(src) : "memory");
}
__device__ __forceinline__ void cp_commit() {
    asm volatile("cp.async.commit_group;" ::: "memory");
}
template<int N> __device__ __forceinline__ void cp_wait() {
    asm volatile("cp.async.wait_group %0;" :: "n"(N) : "memory");
}

#define SWZ(o)   ((o) ^ (((o) >> 3) & 0x70))

// fp32 pair -> packed fp16 hi + fp16 lo (residual)
__device__ __forceinline__ void pack_hl16(float x, float y, uint32_t& h, uint32_t& l) {
    __half2 hh = __floats2half2_rn(x, y);
    float2 f = __half22float2(hh);
    __half2 ll = __floats2half2_rn(x - f.x, y - f.y);
    h = *reinterpret_cast<uint32_t*>(&hh);
    l = *reinterpret_cast<uint32_t*>(&ll);
}

__device__ __forceinline__ float2 unpack_hl16(uint32_t h, uint32_t l) {
    __half2 hh = *reinterpret_cast<__half2*>(&h);
    __half2 ll = *reinterpret_cast<__half2*>(&l);
    float2 a = __half22float2(hh);
    float2 b = __half22float2(ll);
    return make_float2(a.x + b.x, a.y + b.y);
}

// ---------------------------------------------------------------------------
// converters
// ---------------------------------------------------------------------------
__global__ void __launch_bounds__(256)
cvt_hl16(const float* __restrict__ src, __half* __restrict__ h,
         __half* __restrict__ l, int npairs)
{
    const int i = blockIdx.x * 256 + threadIdx.x;
    if (i >= npairs) return;
    float2 v = ((const float2*)src)[i];
    uint32_t hh, ll;
    pack_hl16(v.x, v.y, hh, ll);
    ((uint32_t*)h)[i] = hh;
    ((uint32_t*)l)[i] = ll;
}

__global__ void __launch_bounds__(256)
cvt_16(const float* __restrict__ src, __half* __restrict__ w, int npairs)
{
    const int i = blockIdx.x * 256 + threadIdx.x;
    if (i >= npairs) return;
    float2 v = ((const float2*)src)[i];
    __half2 w2 = __floats2half2_rn(v.x, v.y);
    ((uint32_t*)w)[i] = *reinterpret_cast<uint32_t*>(&w2);
}

// ---------------------------------------------------------------------------
// fp16x2 NT GEMM: C[M,N] = (Ah+Al)[M,K] * B[N,K]^T + bias[N]  (2 products)
// 128x128 tile, BK=64, 256 threads (2x4 warps, warp tile 64x32),
// 3-stage cp.async pipeline (48KB/stage: Ah 16K, Al 16K, B 16K).
// OUT_HL: write fp16 hi/lo else fp32.
// ---------------------------------------------------------------------------
static constexpr int GSTAGE = 49152;
static constexpr int GEMM_SMEM_BYTES = 1024 + 3 * GSTAGE;   // 148480

__device__ __forceinline__ void gemm_issue(
    uint32_t stg, const __half* a0, const __half* a1,
    const __half* b0, int KDIM, int tid)
{
    const __half* base[3] = {a0, a1, b0};
#pragma unroll
    for (int t4 = 0; t4 < 3; ++t4) {
        const uint32_t tb = stg + t4 * 16384;
        const __half* src = base[t4];
#pragma unroll
        for (int it = 0; it < 4; ++it) {
            const int idx = it * 256 + tid;
            const int row = idx >> 3, ch = idx & 7;
            cp16(tb + SWZ((uint32_t)(row * 128 + ch * 16)),
                 src + (size_t)row * KDIM + ch * 8);
        }
    }
}

template<int NDIM, int KDIM, bool OUT_HL>
__global__ void __launch_bounds__(256, 1)
gemm_f16(const __half* __restrict__ Ah, const __half* __restrict__ Al,
         const __half* __restrict__ B16,
         const float* __restrict__ bias, float* __restrict__ C,
         __half* __restrict__ Ch, __half* __restrict__ Cl)
{
    extern __shared__ char smem_raw[];
    const uint32_t sb = (smem_u32(smem_raw) + 1023u) & ~1023u;

    const int tid  = threadIdx.x;
    const int wid  = tid >> 5;
    const int lane = tid & 31;
    const int m0 = blockIdx.y * 128;
    const int n0 = blockIdx.x * 128;
    const int wm = (wid >> 2) * 64;
    const int wn = (wid & 3) * 32;

    const __half* A0 = Ah  + (size_t)m0 * KDIM;
    const __half* A1 = Al  + (size_t)m0 * KDIM;
    const __half* B0 = B16 + (size_t)n0 * KDIM;

    float acc[4][4][4];
#pragma unroll
    for (int i = 0; i < 4; ++i)
#pragma unroll
        for (int j = 0; j < 4; ++j)
#pragma unroll
            for (int r = 0; r < 4; ++r) acc[i][j][r] = 0.f;

    const int lrow16 = lane & 15;
    const int khalfB = (lane >> 4) * 16;
    const int ITERS = KDIM / 64;

    gemm_issue(sb,              A0,       A1,       B0,       KDIM, tid); cp_commit();
    gemm_issue(sb + GSTAGE,     A0 + 64,  A1 + 64,  B0 + 64,  KDIM, tid); cp_commit();
    gemm_issue(sb + 2 * GSTAGE, A0 + 128, A1 + 128, B0 + 128, KDIM, tid); cp_commit();

    for (int kt = 0; kt < ITERS; ++kt) {
        const int sidx = kt % 3;
        const uint32_t stg = sb + sidx * GSTAGE;
        cp_wait<2>();
        __syncthreads();

#pragma unroll
        for (int s = 0; s < 4; ++s) {
            const uint32_t kb = (uint32_t)(s * 32 + khalfB);
            uint32_t bh[2][4];
#pragma unroll
            for (int nj2 = 0; nj2 < 2; ++nj2) {
                const uint32_t roff = SWZ((uint32_t)((wn + nj2 * 16 + lrow16) * 128) + kb);
                ldmatrix_x4(bh[nj2][0], bh[nj2][1], bh[nj2][2], bh[nj2][3],
                            stg + 32768 + roff);
            }
#pragma unroll
            for (int mi = 0; mi < 4; ++mi) {
                const uint32_t aoff = SWZ((uint32_t)((wm + mi * 16 + lrow16) * 128) + kb);
                uint32_t ah[4], al[4];
                ldmatrix_x4(ah[0], ah[1], ah[2], ah[3], stg + aoff);
                ldmatrix_x4(al[0], al[1], al[2], al[3], stg + 16384 + aoff);
#pragma unroll
                for (int nj = 0; nj < 4; ++nj)
                    mma16816f(acc[mi][nj], ah,
                              bh[nj >> 1][nj & 1], bh[nj >> 1][(nj & 1) + 2]);
#pragma unroll
                for (int nj = 0; nj < 4; ++nj)
                    mma16816f(acc[mi][nj], al,
                              bh[nj >> 1][nj & 1], bh[nj >> 1][(nj & 1) + 2]);
            }
        }

        __syncthreads();
        if (kt + 3 < ITERS) {
            const int ko = (kt + 3) * 64;
            gemm_issue(stg, A0 + ko, A1 + ko, B0 + ko, KDIM, tid);
        }
        cp_commit();
    }

    // epilogue
    const int qrow = lane >> 2;
    const int qcol = (lane & 3) * 2;
#pragma unroll
    for (int mi = 0; mi < 4; ++mi) {
        const int r0 = m0 + wm + mi * 16 + qrow;
#pragma unroll
        for (int nj = 0; nj < 4; ++nj) {
            const int c0 = n0 + wn + nj * 8 + qcol;
            const float bx = bias[c0], by = bias[c0 + 1];
            const float v00 = acc[mi][nj][0] + bx, v01 = acc[mi][nj][1] + by;
            const float v10 = acc[mi][nj][2] + bx, v11 = acc[mi][nj][3] + by;
            if (OUT_HL) {
                uint32_t h, l;
                pack_hl16(v00, v01, h, l);
                *(uint32_t*)(Ch + (size_t)r0 * NDIM + c0) = h;
                *(uint32_t*)(Cl + (size_t)r0 * NDIM + c0) = l;
                pack_hl16(v10, v11, h, l);
                *(uint32_t*)(Ch + (size_t)(r0 + 8) * NDIM + c0) = h;
                *(uint32_t*)(Cl + (size_t)(r0 + 8) * NDIM + c0) = l;
            } else {
                *(float2*)&C[(size_t)r0 * NDIM + c0]       = make_float2(v00, v01);
                *(float2*)&C[(size_t)(r0 + 8) * NDIM + c0] = make_float2(v10, v11);
            }
        }
    }
}

// ---------------------------------------------------------------------------
// RoPE in-place on qkv hi/lo (fp16). One warp per (token, rope-slot).
// ---------------------------------------------------------------------------
__global__ void __launch_bounds__(256)
rope_hl(__half* __restrict__ qh, __half* __restrict__ ql,
        const float* __restrict__ cosb, const float* __restrict__ sinb)
{
    const int gid  = blockIdx.x * 8 + (threadIdx.x >> 5);
    const int lane = threadIdx.x & 31;
    const int t   = gid / 40;
    const int s40 = gid % 40;
    const int ss  = s40 % 5;             // 0-3 q, 4 k
    const int slot = (s40 / 5) * 6 + ss;
    const int d = 2 * lane;

    const size_t off = (size_t)t * QKVD + slot * 64 + d;
    uint32_t h = *(const uint32_t*)(qh + off);
    uint32_t l = *(const uint32_t*)(ql + off);
    float2 v = unpack_hl16(h, l);

    float px = __shfl_xor_sync(0xffffffffu, v.x, 4);
    float py = __shfl_xor_sync(0xffffffffu, v.y, 4);
    if (d < 16) {
        const float rx = (d < 8) ? -px : px;
        const float ry = (d < 8) ? -py : py;
        const float c0 = cosb[t * 16 + d],     s0 = sinb[t * 16 + d];
        const float c1 = cosb[t * 16 + d + 1], s1 = sinb[t * 16 + d + 1];
        v.x = v.x * c0 + rx * s0;
        v.y = v.y * c1 + ry * s1;
    }
    if (ss < 4) { v.x *= 0.125f; v.y *= 0.125f; }

    pack_hl16(v.x, v.y, h, l);
    *(uint32_t*)(qh + off) = h;
    *(uint32_t*)(ql + off) = l;
}

// ---------------------------------------------------------------------------
// Flash attention, causal, fp16x2: S = (Qh+Ql)*Kh (2 prod), O = P*(Vh+Vl)
// (2 prod). KV stage: [Kh 16K][Vh 16K][Vl 16K] = 48KB, double-buffered.
// ---------------------------------------------------------------------------
static constexpr int FL_STAGE = 49152;
static constexpr int FLASH_SMEM_BYTES = 1024 + 32768 + 2 * FL_STAGE;   // 131072+1024

__device__ __forceinline__ void flash_issue_kv(
    uint32_t SB, const __half* qh, const __half* ql,
    int n0, int koff, int voff, int tid)
{
#pragma unroll
    for (int p = 0; p < 4; ++p) {
        const int idx = p * 256 + tid;
        const int row = idx >> 3, ch = idx & 7;
        const uint32_t off = SWZ((uint32_t)(row * 128 + ch * 16));
        const size_t gk = (size_t)(n0 + row) * QKVD + koff + ch * 8;
        const size_t gv = (size_t)(n0 + row) * QKVD + voff + ch * 8;
        cp16(SB + off,         qh + gk);   // K hi (single-rounded K)
        cp16(SB + 16384 + off, qh + gv);   // V hi
        cp16(SB + 32768 + off, ql + gv);   // V lo
    }
}

__global__ void __launch_bounds__(256, 1)
flash_mma(const __half* __restrict__ qh,
          const __half* __restrict__ ql,
          __half* __restrict__ yh, __half* __restrict__ yl)
{
    extern __shared__ char smem_raw[];
    const uint32_t sb = (smem_u32(smem_raw) + 1023u) & ~1023u;

    const int tid  = threadIdx.x;
    const int wid  = tid >> 5;
    const int lane = tid & 31;
    const int h  = blockIdx.x;
    const int m0 = (15 - (int)blockIdx.y) * 128;
    const int nb = m0 / 128 + 1;
    const int g = h >> 2;
    const int qoff = g * 384 + (h & 3) * 64;
    const int koff = g * 384 + 256;
    const int voff = g * 384 + 320;
    const int wm = wid * 16;

#pragma unroll
    for (int p = 0; p < 4; ++p) {
        const int idx = p * 256 + tid;
        const int row = idx >> 3, ch = idx & 7;
        const uint32_t off = SWZ((uint32_t)(row * 128 + ch * 16));
        const size_t gq = (size_t)(m0 + row) * QKVD + qoff + ch * 8;
        cp16(sb + off,         qh + gq);
        cp16(sb + 16384 + off, ql + gq);
    }
    flash_issue_kv(sb + 32768, qh, ql, 0, koff, voff, tid);
    cp_commit();
    if (nb > 1) {
        flash_issue_kv(sb + 32768 + FL_STAGE, qh, ql, 128, koff, voff, tid);
        cp_commit();
        cp_wait<1>();
    } else {
        cp_wait<0>();
    }
    __syncthreads();

    uint32_t qfh[4][4], qfl[4][4];
#pragma unroll
    for (int s = 0; s < 4; ++s) {
        const uint32_t aoff = SWZ((uint32_t)((wm + (lane & 15)) * 128
                                             + s * 32 + (lane >> 4) * 16));
        ldmatrix_x4(qfh[s][0], qfh[s][1], qfh[s][2], qfh[s][3], sb + aoff);
        ldmatrix_x4(qfl[s][0], qfl[s][1], qfl[s][2], qfl[s][3], sb + 16384 + aoff);
    }

    float O[8][4];
#pragma unroll
    for (int nj = 0; nj < 8; ++nj)
#pragma unroll
        for (int r = 0; r < 4; ++r) O[nj][r] = 0.f;
    float m_0 = -1e30f, m_1 = -1e30f, l_0 = 0.f, l_1 = 0.f;

    for (int kt = 0; kt < nb; ++kt) {
        const uint32_t SB = sb + 32768 + (kt & 1) * FL_STAGE;
        const uint32_t VB = SB + 16384;

        float S[16][4];
#pragma unroll
        for (int nf = 0; nf < 16; ++nf)
#pragma unroll
            for (int r = 0; r < 4; ++r) S[nf][r] = 0.f;

#pragma unroll
        for (int s = 0; s < 4; ++s) {
            const uint32_t kb = (uint32_t)(s * 32 + (lane >> 4) * 16);
#pragma unroll
            for (int njp = 0; njp < 8; ++njp) {
                const uint32_t roff = SWZ((uint32_t)((njp * 16 + (lane & 15)) * 128) + kb);
                uint32_t kh[4];
                ldmatrix_x4(kh[0], kh[1], kh[2], kh[3], SB + roff);
                // 2 products, acc-interleaved
                mma16816f(S[2 * njp],     qfh[s], kh[0], kh[2]);
                mma16816f(S[2 * njp + 1], qfh[s], kh[1], kh[3]);
                mma16816f(S[2 * njp],     qfl[s], kh[0], kh[2]);
                mma16816f(S[2 * njp + 1], qfl[s], kh[1], kh[3]);
            }
        }

        if (kt == nb - 1) {
            const int bc = 2 * (lane & 3);
            const int lim0 = wm + (lane >> 2);
            const int lim1 = lim0 + 8;
#pragma unroll
            for (int nf = 0; nf < 16; ++nf) {
                const int c0 = nf * 8 + bc;
                if (c0 > lim0)     S[nf][0] = -1e30f;
                if (c0 + 1 > lim0) S[nf][1] = -1e30f;
                if (c0 > lim1)     S[nf][2] = -1e30f;
                if (c0 + 1 > lim1) S[nf][3] = -1e30f;
            }
        }

        float mx0 = -1e30f, mx1 = -1e30f;
#pragma unroll
        for (int nf = 0; nf < 16; ++nf) {
            mx0 = fmaxf(mx0, fmaxf(S[nf][0], S[nf][1]));
            mx1 = fmaxf(mx1, fmaxf(S[nf][2], S[nf][3]));
        }
        mx0 = fmaxf(mx0, __shfl_xor_sync(0xffffffffu, mx0, 1));
        mx0 = fmaxf(mx0, __shfl_xor_sync(0xffffffffu, mx0, 2));
        mx1 = fmaxf(mx1, __shfl_xor_sync(0xffffffffu, mx1, 1));
        mx1 = fmaxf(mx1, __shfl_xor_sync(0xffffffffu, mx1, 2));
        const float mn0 = fmaxf(m_0, mx0), mn1 = fmaxf(m_1, mx1);
        const float f0 = __expf(m_0 - mn0), f1 = __expf(m_1 - mn1);
        m_0 = mn0; m_1 = mn1;

        float rs0 = 0.f, rs1 = 0.f;
#pragma unroll
        for (int nf = 0; nf < 16; ++nf) {
            S[nf][0] = __expf(S[nf][0] - mn0);
            S[nf][1] = __expf(S[nf][1] - mn0);
            S[nf][2] = __expf(S[nf][2] - mn1);
            S[nf][3] = __expf(S[nf][3] - mn1);
            rs0 += S[nf][0] + S[nf][1];
            rs1 += S[nf][2] + S[nf][3];
        }
        rs0 += __shfl_xor_sync(0xffffffffu, rs0, 1);
        rs0 += __shfl_xor_sync(0xffffffffu, rs0, 2);
        rs1 += __shfl_xor_sync(0xffffffffu, rs1, 1);
        rs1 += __shfl_xor_sync(0xffffffffu, rs1, 2);
        l_0 = l_0 * f0 + rs0;
        l_1 = l_1 * f1 + rs1;
#pragma unroll
        for (int nj = 0; nj < 8; ++nj) {
            O[nj][0] *= f0; O[nj][1] *= f0;
            O[nj][2] *= f1; O[nj][3] *= f1;
        }

        const uint32_t kr   = (uint32_t)(((lane & 8) ? 8 : 0) + (lane & 7));
        const uint32_t dsel = (lane & 16) ? 8u : 0u;
#pragma unroll
        for (int t = 0; t < 8; ++t) {
            // P single-rounded fp16
            uint32_t ph[4];
            {
                __half2 p0 = __floats2half2_rn(S[2 * t][0],     S[2 * t][1]);
                __half2 p1 = __floats2half2_rn(S[2 * t][2],     S[2 * t][3]);
                __half2 p2 = __floats2half2_rn(S[2 * t + 1][0], S[2 * t + 1][1]);
                __half2 p3 = __floats2half2_rn(S[2 * t + 1][2], S[2 * t + 1][3]);
                ph[0] = *reinterpret_cast<uint32_t*>(&p0);
                ph[1] = *reinterpret_cast<uint32_t*>(&p1);
                ph[2] = *reinterpret_cast<uint32_t*>(&p2);
                ph[3] = *reinterpret_cast<uint32_t*>(&p3);
            }
#pragma unroll
            for (int db = 0; db < 64; db += 16) {
                const uint32_t voff2 = SWZ((uint32_t)((t * 16 + kr) * 128
                                                      + (db + dsel) * 2));
                uint32_t vh[4], vl[4];
                ldmatrix_x4_t(vh[0], vh[1], vh[2], vh[3], VB + voff2);
                ldmatrix_x4_t(vl[0], vl[1], vl[2], vl[3], VB + 16384 + voff2);
                const int oj = db / 8;
                // 2 products, acc-interleaved
                mma16816f(O[oj],     ph, vh[0], vh[1]);
                mma16816f(O[oj + 1], ph, vh[2], vh[3]);
                mma16816f(O[oj],     ph, vl[0], vl[1]);
                mma16816f(O[oj + 1], ph, vl[2], vl[3]);
            }
        }

        __syncthreads();
        if (kt + 1 < nb) {
            if (kt + 2 < nb) {
                flash_issue_kv(sb + 32768 + (kt & 1) * FL_STAGE, qh, ql,
                               (kt + 2) * 128, koff, voff, tid);
                cp_commit();
                cp_wait<1>();
            } else {
                cp_wait<0>();
            }
            __syncthreads();
        }
    }

    const float inv0 = 1.f / l_0, inv1 = 1.f / l_1;
    const int r0 = m0 + wm + (lane >> 2);
    const int col0 = h * 64 + 2 * (lane & 3);
#pragma unroll
    for (int nj = 0; nj < 8; ++nj) {
        const int col = col0 + nj * 8;
        uint32_t hh, ll;
        pack_hl16(O[nj][0] * inv0, O[nj][1] * inv0, hh, ll);
        *(uint32_t*)(yh + (size_t)r0 * CDIM + col) = hh;
        *(uint32_t*)(yl + (size_t)r0 * CDIM + col) = ll;
        pack_hl16(O[nj][2] * inv1, O[nj][3] * inv1, hh, ll);
        *(uint32_t*)(yh + (size_t)(r0 + 8) * CDIM + col) = hh;
        *(uint32_t*)(yl + (size_t)(r0 + 8) * CDIM + col) = ll;
    }
}

// ---------------------------------------------------------------------------
extern "C" void kernel_launch(void* const* d_in, const int* in_sizes, int n_in,
                              void* d_out, int out_size)
{
    const float* x      = (const float*)d_in[0];
    const float* cosb   = (const float*)d_in[1];
    const float* sinb   = (const float*)d_in[2];
    const float* W_attn = (const float*)d_in[3];
    const float* b_attn = (const float*)d_in[4];
    const float* W_proj = (const float*)d_in[5];
    const float* b_proj = (const float*)d_in[6];
    float* out = (float*)d_out;

    __half *qh, *ql, *xh, *xl, *wa, *wp, *yh, *yl;
    cudaGetSymbolAddress((void**)&qh, g_qh);
    cudaGetSymbolAddress((void**)&ql, g_ql);
    cudaGetSymbolAddress((void**)&xh, g_xh);
    cudaGetSymbolAddress((void**)&xl, g_xl);
    cudaGetSymbolAddress((void**)&wa, g_wa);
    cudaGetSymbolAddress((void**)&wp, g_wp);
    cudaGetSymbolAddress((void**)&yh, g_yh);
    cudaGetSymbolAddress((void**)&yl, g_yl);

    cudaFuncSetAttribute(gemm_f16<QKVD, CDIM, true>,
                         cudaFuncAttributeMaxDynamicSharedMemorySize, GEMM_SMEM_BYTES);
    cudaFuncSetAttribute(gemm_f16<CDIM, CDIM, false>,
                         cudaFuncAttributeMaxDynamicSharedMemorySize, GEMM_SMEM_BYTES);
    cudaFuncSetAttribute(flash_mma,
                         cudaFuncAttributeMaxDynamicSharedMemorySize, FLASH_SMEM_BYTES);

    // 0) converts: x -> fp16 hi/lo; weights -> fp16 single
    cvt_hl16<<<(TSEQ * CDIM / 2 + 255) / 256, 256>>>(x, xh, xl, TSEQ * CDIM / 2);
    cvt_16<<<(QKVD * CDIM / 2 + 255) / 256, 256>>>(W_attn, wa, QKVD * CDIM / 2);
    cvt_16<<<(CDIM * CDIM / 2 + 255) / 256, 256>>>(W_proj, wp, CDIM * CDIM / 2);

    // 1) QKV GEMM + bias -> fp16 hi/lo qkv (fp16x2 compute)
    gemm_f16<QKVD, CDIM, true>
        <<<dim3(QKVD / 128, TSEQ / 128), 256, GEMM_SMEM_BYTES>>>(
            xh, xl, wa, b_attn, nullptr, qh, ql);

    // 2) RoPE in place on fp16 hi/lo (scale folded into Q)
    rope_hl<<<TSEQ * 40 / 8, 256>>>(qh, ql, cosb, sinb);

    // 3) causal flash attention (fp16x2) -> fp16 hi/lo y
    flash_mma<<<dim3(NHEAD, TSEQ / 128), 256, FLASH_SMEM_BYTES>>>(qh, ql, yh, yl);

    // 4) output projection + bias -> fp32 out (fp16x2 compute)
    gemm_f16<CDIM, CDIM, false>
        <<<dim3(CDIM / 128, TSEQ / 128), 256, GEMM_SMEM_BYTES>>>(
            yh, yl, wp, b_proj, out, nullptr, nullptr);
}

// round 16
// speedup vs baseline: 2.0239x; 1.4518x over previous
#include <cuda_runtime.h>
#include <cuda_bf16.h>
#include <cuda_fp16.h>
#include <math.h>
#include <stdint.h>

#define TSEQ 2048
#define CDIM 2048
#define QKVD 3072
#define NHEAD 32
#define HSZ 64

// scratch (no allocations allowed) — all fp16
__device__ __half g_qh[TSEQ * QKVD];   // qkv hi
__device__ __half g_ql[TSEQ * QKVD];   // qkv lo
__device__ __half g_x16[TSEQ * CDIM];  // x (single-rounded fp16)
__device__ __half g_wa[QKVD * CDIM];   // W_attn (single)
__device__ __half g_wp[CDIM * CDIM];   // W_proj (single)
__device__ __half g_y16[TSEQ * CDIM];  // attn out (single-rounded fp16)

// ---------------------------------------------------------------------------
// helpers
// ---------------------------------------------------------------------------
__device__ __forceinline__ uint32_t smem_u32(const void* p) {
    uint32_t a;
    asm("{ .reg .u64 t; cvta.to.shared.u64 t, %1; cvt.u32.u64 %0, t; }"
        : "=r"(a) : "l"(p));
    return a;
}

__device__ __forceinline__ void ldmatrix_x4(uint32_t& r0, uint32_t& r1,
                                            uint32_t& r2, uint32_t& r3,
                                            uint32_t addr) {
    asm volatile("ldmatrix.sync.aligned.m8n8.x4.shared.b16 {%0,%1,%2,%3}, [%4];"
                 : "=r"(r0), "=r"(r1), "=r"(r2), "=r"(r3) : "r"(addr));
}

__device__ __forceinline__ void ldmatrix_x4_t(uint32_t& r0, uint32_t& r1,
                                              uint32_t& r2, uint32_t& r3,
                                              uint32_t addr) {
    asm volatile("ldmatrix.sync.aligned.m8n8.x4.trans.shared.b16 {%0,%1,%2,%3}, [%4];"
                 : "=r"(r0), "=r"(r1), "=r"(r2), "=r"(r3) : "r"(addr));
}

// fp16 mma
__device__ __forceinline__ void mma16816f(float* c, const uint32_t* a,
                                          uint32_t b0, uint32_t b1) {
    asm volatile(
        "mma.sync.aligned.m16n8k16.row.col.f32.f16.f16.f32 "
        "{%0,%1,%2,%3}, {%4,%5,%6,%7}, {%8,%9}, {%0,%1,%2,%3};"
        : "+f"(c[0]), "+f"(c[1]), "+f"(c[2]), "+f"(c[3])
        : "r"(a[0]), "r"(a[1]), "r"(a[2]), "r"(a[3]), "r"(b0), "r"(b1));
}

__device__ __forceinline__ void cp16(uint32_t dst, const void* src) {
    asm volatile("cp.async.cg.shared.global [%0], [%1], 16;"
                 :: "r"(dst), "l"(src) : "memory");
}
__device__ __forceinline__ void cp_commit() {
    asm volatile("cp.async.commit_group;" ::: "memory");
}
template<int N> __device__ __forceinline__ void cp_wait() {
    asm volatile("cp.async.wait_group %0;" :: "n"(N) : "memory");
}

#define SWZ(o)   ((o) ^ (((o) >> 3) & 0x70))

// fp32 pair -> packed fp16 hi + fp16 lo (residual)
__device__ __forceinline__ void pack_hl16(float x, float y, uint32_t& h, uint32_t& l) {
    __half2 hh = __floats2half2_rn(x, y);
    float2 f = __half22float2(hh);
    __half2 ll = __floats2half2_rn(x - f.x, y - f.y);
    h = *reinterpret_cast<uint32_t*>(&hh);
    l = *reinterpret_cast<uint32_t*>(&ll);
}

__device__ __forceinline__ float2 unpack_hl16(uint32_t h, uint32_t l) {
    __half2 hh = *reinterpret_cast<__half2*>(&h);
    __half2 ll = *reinterpret_cast<__half2*>(&l);
    float2 a = __half22float2(hh);
    float2 b = __half22float2(ll);
    return make_float2(a.x + b.x, a.y + b.y);
}

// ---------------------------------------------------------------------------
// converter: fp32 -> fp16 single
// ---------------------------------------------------------------------------
__global__ void __launch_bounds__(256)
cvt_16(const float* __restrict__ src, __half* __restrict__ w, int npairs)
{
    const int i = blockIdx.x * 256 + threadIdx.x;
    if (i >= npairs) return;
    float2 v = ((const float2*)src)[i];
    __half2 w2 = __floats2half2_rn(v.x, v.y);
    ((uint32_t*)w)[i] = *reinterpret_cast<uint32_t*>(&w2);
}

// ---------------------------------------------------------------------------
// fp16 single-product NT GEMM: C[M,N] = A[M,K]*B[N,K]^T + bias[N]
// 128x128 tile, BK=64, 256 threads (2x4 warps, warp tile 64x32),
// 3-stage cp.async pipeline (32KB/stage: A 16K, B 16K).
// OUT_HL: write fp16 hi/lo else fp32.
// ---------------------------------------------------------------------------
static constexpr int GSTAGE = 32768;
static constexpr int GEMM_SMEM_BYTES = 1024 + 3 * GSTAGE;   // 99328

__device__ __forceinline__ void gemm_issue(
    uint32_t stg, const __half* a0, const __half* b0, int KDIM, int tid)
{
    const __half* base[2] = {a0, b0};
#pragma unroll
    for (int t2 = 0; t2 < 2; ++t2) {
        const uint32_t tb = stg + t2 * 16384;
        const __half* src = base[t2];
#pragma unroll
        for (int it = 0; it < 4; ++it) {
            const int idx = it * 256 + tid;
            const int row = idx >> 3, ch = idx & 7;
            cp16(tb + SWZ((uint32_t)(row * 128 + ch * 16)),
                 src + (size_t)row * KDIM + ch * 8);
        }
    }
}

template<int NDIM, int KDIM, bool OUT_HL>
__global__ void __launch_bounds__(256, 1)
gemm_f16(const __half* __restrict__ A16, const __half* __restrict__ B16,
         const float* __restrict__ bias, float* __restrict__ C,
         __half* __restrict__ Ch, __half* __restrict__ Cl)
{
    extern __shared__ char smem_raw[];
    const uint32_t sb = (smem_u32(smem_raw) + 1023u) & ~1023u;

    const int tid  = threadIdx.x;
    const int wid  = tid >> 5;
    const int lane = tid & 31;
    const int m0 = blockIdx.y * 128;
    const int n0 = blockIdx.x * 128;
    const int wm = (wid >> 2) * 64;
    const int wn = (wid & 3) * 32;

    const __half* A0 = A16 + (size_t)m0 * KDIM;
    const __half* B0 = B16 + (size_t)n0 * KDIM;

    float acc[4][4][4];
#pragma unroll
    for (int i = 0; i < 4; ++i)
#pragma unroll
        for (int j = 0; j < 4; ++j)
#pragma unroll
            for (int r = 0; r < 4; ++r) acc[i][j][r] = 0.f;

    const int lrow16 = lane & 15;
    const int khalfB = (lane >> 4) * 16;
    const int ITERS = KDIM / 64;

    gemm_issue(sb,              A0,       B0,       KDIM, tid); cp_commit();
    gemm_issue(sb + GSTAGE,     A0 + 64,  B0 + 64,  KDIM, tid); cp_commit();
    gemm_issue(sb + 2 * GSTAGE, A0 + 128, B0 + 128, KDIM, tid); cp_commit();

    for (int kt = 0; kt < ITERS; ++kt) {
        const int sidx = kt % 3;
        const uint32_t stg = sb + sidx * GSTAGE;
        cp_wait<2>();
        __syncthreads();

#pragma unroll
        for (int s = 0; s < 4; ++s) {
            const uint32_t kb = (uint32_t)(s * 32 + khalfB);
            uint32_t bh[2][4];
#pragma unroll
            for (int nj2 = 0; nj2 < 2; ++nj2) {
                const uint32_t roff = SWZ((uint32_t)((wn + nj2 * 16 + lrow16) * 128) + kb);
                ldmatrix_x4(bh[nj2][0], bh[nj2][1], bh[nj2][2], bh[nj2][3],
                            stg + 16384 + roff);
            }
#pragma unroll
            for (int mi = 0; mi < 4; ++mi) {
                const uint32_t aoff = SWZ((uint32_t)((wm + mi * 16 + lrow16) * 128) + kb);
                uint32_t ah[4];
                ldmatrix_x4(ah[0], ah[1], ah[2], ah[3], stg + aoff);
#pragma unroll
                for (int nj = 0; nj < 4; ++nj)
                    mma16816f(acc[mi][nj], ah,
                              bh[nj >> 1][nj & 1], bh[nj >> 1][(nj & 1) + 2]);
            }
        }

        __syncthreads();
        if (kt + 3 < ITERS) {
            const int ko = (kt + 3) * 64;
            gemm_issue(stg, A0 + ko, B0 + ko, KDIM, tid);
        }
        cp_commit();
    }

    // epilogue
    const int qrow = lane >> 2;
    const int qcol = (lane & 3) * 2;
#pragma unroll
    for (int mi = 0; mi < 4; ++mi) {
        const int r0 = m0 + wm + mi * 16 + qrow;
#pragma unroll
        for (int nj = 0; nj < 4; ++nj) {
            const int c0 = n0 + wn + nj * 8 + qcol;
            const float bx = bias[c0], by = bias[c0 + 1];
            const float v00 = acc[mi][nj][0] + bx, v01 = acc[mi][nj][1] + by;
            const float v10 = acc[mi][nj][2] + bx, v11 = acc[mi][nj][3] + by;
            if (OUT_HL) {
                uint32_t h, l;
                pack_hl16(v00, v01, h, l);
                *(uint32_t*)(Ch + (size_t)r0 * NDIM + c0) = h;
                *(uint32_t*)(Cl + (size_t)r0 * NDIM + c0) = l;
                pack_hl16(v10, v11, h, l);
                *(uint32_t*)(Ch + (size_t)(r0 + 8) * NDIM + c0) = h;
                *(uint32_t*)(Cl + (size_t)(r0 + 8) * NDIM + c0) = l;
            } else {
                *(float2*)&C[(size_t)r0 * NDIM + c0]       = make_float2(v00, v01);
                *(float2*)&C[(size_t)(r0 + 8) * NDIM + c0] = make_float2(v10, v11);
            }
        }
    }
}

// ---------------------------------------------------------------------------
// RoPE in-place on qkv hi/lo (fp16). One warp per (token, rope-slot).
// ---------------------------------------------------------------------------
__global__ void __launch_bounds__(256)
rope_hl(__half* __restrict__ qh, __half* __restrict__ ql,
        const float* __restrict__ cosb, const float* __restrict__ sinb)
{
    const int gid  = blockIdx.x * 8 + (threadIdx.x >> 5);
    const int lane = threadIdx.x & 31;
    const int t   = gid / 40;
    const int s40 = gid % 40;
    const int ss  = s40 % 5;             // 0-3 q, 4 k
    const int slot = (s40 / 5) * 6 + ss;
    const int d = 2 * lane;

    const size_t off = (size_t)t * QKVD + slot * 64 + d;
    uint32_t h = *(const uint32_t*)(qh + off);
    uint32_t l = *(const uint32_t*)(ql + off);
    float2 v = unpack_hl16(h, l);

    float px = __shfl_xor_sync(0xffffffffu, v.x, 4);
    float py = __shfl_xor_sync(0xffffffffu, v.y, 4);
    if (d < 16) {
        const float rx = (d < 8) ? -px : px;
        const float ry = (d < 8) ? -py : py;
        const float c0 = cosb[t * 16 + d],     s0 = sinb[t * 16 + d];
        const float c1 = cosb[t * 16 + d + 1], s1 = sinb[t * 16 + d + 1];
        v.x = v.x * c0 + rx * s0;
        v.y = v.y * c1 + ry * s1;
    }
    if (ss < 4) { v.x *= 0.125f; v.y *= 0.125f; }

    pack_hl16(v.x, v.y, h, l);
    *(uint32_t*)(qh + off) = h;
    *(uint32_t*)(ql + off) = l;
}

// ---------------------------------------------------------------------------
// Flash attention, causal, fp16x2: S = (Qh+Ql)*Kh (2 prod), O = P*(Vh+Vl)
// (2 prod). KV stage: [Kh 16K][Vh 16K][Vl 16K] = 48KB, double-buffered.
// Output: single-rounded fp16 y.
// ---------------------------------------------------------------------------
static constexpr int FL_STAGE = 49152;
static constexpr int FLASH_SMEM_BYTES = 1024 + 32768 + 2 * FL_STAGE;

__device__ __forceinline__ void flash_issue_kv(
    uint32_t SB, const __half* qh, const __half* ql,
    int n0, int koff, int voff, int tid)
{
#pragma unroll
    for (int p = 0; p < 4; ++p) {
        const int idx = p * 256 + tid;
        const int row = idx >> 3, ch = idx & 7;
        const uint32_t off = SWZ((uint32_t)(row * 128 + ch * 16));
        const size_t gk = (size_t)(n0 + row) * QKVD + koff + ch * 8;
        const size_t gv = (size_t)(n0 + row) * QKVD + voff + ch * 8;
        cp16(SB + off,         qh + gk);   // K hi
        cp16(SB + 16384 + off, qh + gv);   // V hi
        cp16(SB + 32768 + off, ql + gv);   // V lo
    }
}

__global__ void __launch_bounds__(256, 1)
flash_mma(const __half* __restrict__ qh,
          const __half* __restrict__ ql,
          __half* __restrict__ y16)
{
    extern __shared__ char smem_raw[];
    const uint32_t sb = (smem_u32(smem_raw) + 1023u) & ~1023u;

    const int tid  = threadIdx.x;
    const int wid  = tid >> 5;
    const int lane = tid & 31;
    const int h  = blockIdx.x;
    const int m0 = (15 - (int)blockIdx.y) * 128;
    const int nb = m0 / 128 + 1;
    const int g = h >> 2;
    const int qoff = g * 384 + (h & 3) * 64;
    const int koff = g * 384 + 256;
    const int voff = g * 384 + 320;
    const int wm = wid * 16;

#pragma unroll
    for (int p = 0; p < 4; ++p) {
        const int idx = p * 256 + tid;
        const int row = idx >> 3, ch = idx & 7;
        const uint32_t off = SWZ((uint32_t)(row * 128 + ch * 16));
        const size_t gq = (size_t)(m0 + row) * QKVD + qoff + ch * 8;
        cp16(sb + off,         qh + gq);
        cp16(sb + 16384 + off, ql + gq);
    }
    flash_issue_kv(sb + 32768, qh, ql, 0, koff, voff, tid);
    cp_commit();
    if (nb > 1) {
        flash_issue_kv(sb + 32768 + FL_STAGE, qh, ql, 128, koff, voff, tid);
        cp_commit();
        cp_wait<1>();
    } else {
        cp_wait<0>();
    }
    __syncthreads();

    uint32_t qfh[4][4], qfl[4][4];
#pragma unroll
    for (int s = 0; s < 4; ++s) {
        const uint32_t aoff = SWZ((uint32_t)((wm + (lane & 15)) * 128
                                             + s * 32 + (lane >> 4) * 16));
        ldmatrix_x4(qfh[s][0], qfh[s][1], qfh[s][2], qfh[s][3], sb + aoff);
        ldmatrix_x4(qfl[s][0], qfl[s][1], qfl[s][2], qfl[s][3], sb + 16384 + aoff);
    }

    float O[8][4];
#pragma unroll
    for (int nj = 0; nj < 8; ++nj)
#pragma unroll
        for (int r = 0; r < 4; ++r) O[nj][r] = 0.f;
    float m_0 = -1e30f, m_1 = -1e30f, l_0 = 0.f, l_1 = 0.f;

    for (int kt = 0; kt < nb; ++kt) {
        const uint32_t SB = sb + 32768 + (kt & 1) * FL_STAGE;
        const uint32_t VB = SB + 16384;

        float S[16][4];
#pragma unroll
        for (int nf = 0; nf < 16; ++nf)
#pragma unroll
            for (int r = 0; r < 4; ++r) S[nf][r] = 0.f;

#pragma unroll
        for (int s = 0; s < 4; ++s) {
            const uint32_t kb = (uint32_t)(s * 32 + (lane >> 4) * 16);
#pragma unroll
            for (int njp = 0; njp < 8; ++njp) {
                const uint32_t roff = SWZ((uint32_t)((njp * 16 + (lane & 15)) * 128) + kb);
                uint32_t kh[4];
                ldmatrix_x4(kh[0], kh[1], kh[2], kh[3], SB + roff);
                mma16816f(S[2 * njp],     qfh[s], kh[0], kh[2]);
                mma16816f(S[2 * njp + 1], qfh[s], kh[1], kh[3]);
                mma16816f(S[2 * njp],     qfl[s], kh[0], kh[2]);
                mma16816f(S[2 * njp + 1], qfl[s], kh[1], kh[3]);
            }
        }

        if (kt == nb - 1) {
            const int bc = 2 * (lane & 3);
            const int lim0 = wm + (lane >> 2);
            const int lim1 = lim0 + 8;
#pragma unroll
            for (int nf = 0; nf < 16; ++nf) {
                const int c0 = nf * 8 + bc;
                if (c0 > lim0)     S[nf][0] = -1e30f;
                if (c0 + 1 > lim0) S[nf][1] = -1e30f;
                if (c0 > lim1)     S[nf][2] = -1e30f;
                if (c0 + 1 > lim1) S[nf][3] = -1e30f;
            }
        }

        float mx0 = -1e30f, mx1 = -1e30f;
#pragma unroll
        for (int nf = 0; nf < 16; ++nf) {
            mx0 = fmaxf(mx0, fmaxf(S[nf][0], S[nf][1]));
            mx1 = fmaxf(mx1, fmaxf(S[nf][2], S[nf][3]));
        }
        mx0 = fmaxf(mx0, __shfl_xor_sync(0xffffffffu, mx0, 1));
        mx0 = fmaxf(mx0, __shfl_xor_sync(0xffffffffu, mx0, 2));
        mx1 = fmaxf(mx1, __shfl_xor_sync(0xffffffffu, mx1, 1));
        mx1 = fmaxf(mx1, __shfl_xor_sync(0xffffffffu, mx1, 2));
        const float mn0 = fmaxf(m_0, mx0), mn1 = fmaxf(m_1, mx1);
        const float f0 = __expf(m_0 - mn0), f1 = __expf(m_1 - mn1);
        m_0 = mn0; m_1 = mn1;

        float rs0 = 0.f, rs1 = 0.f;
#pragma unroll
        for (int nf = 0; nf < 16; ++nf) {
            S[nf][0] = __expf(S[nf][0] - mn0);
            S[nf][1] = __expf(S[nf][1] - mn0);
            S[nf][2] = __expf(S[nf][2] - mn1);
            S[nf][3] = __expf(S[nf][3] - mn1);
            rs0 += S[nf][0] + S[nf][1];
            rs1 += S[nf][2] + S[nf][3];
        }
        rs0 += __shfl_xor_sync(0xffffffffu, rs0, 1);
        rs0 += __shfl_xor_sync(0xffffffffu, rs0, 2);
        rs1 += __shfl_xor_sync(0xffffffffu, rs1, 1);
        rs1 += __shfl_xor_sync(0xffffffffu, rs1, 2);
        l_0 = l_0 * f0 + rs0;
        l_1 = l_1 * f1 + rs1;
#pragma unroll
        for (int nj = 0; nj < 8; ++nj) {
            O[nj][0] *= f0; O[nj][1] *= f0;
            O[nj][2] *= f1; O[nj][3] *= f1;
        }

        const uint32_t kr   = (uint32_t)(((lane & 8) ? 8 : 0) + (lane & 7));
        const uint32_t dsel = (lane & 16) ? 8u : 0u;
#pragma unroll
        for (int t = 0; t < 8; ++t) {
            uint32_t ph[4];
            {
                __half2 p0 = __floats2half2_rn(S[2 * t][0],     S[2 * t][1]);
                __half2 p1 = __floats2half2_rn(S[2 * t][2],     S[2 * t][3]);
                __half2 p2 = __floats2half2_rn(S[2 * t + 1][0], S[2 * t + 1][1]);
                __half2 p3 = __floats2half2_rn(S[2 * t + 1][2], S[2 * t + 1][3]);
                ph[0] = *reinterpret_cast<uint32_t*>(&p0);
                ph[1] = *reinterpret_cast<uint32_t*>(&p1);
                ph[2] = *reinterpret_cast<uint32_t*>(&p2);
                ph[3] = *reinterpret_cast<uint32_t*>(&p3);
            }
#pragma unroll
            for (int db = 0; db < 64; db += 16) {
                const uint32_t voff2 = SWZ((uint32_t)((t * 16 + kr) * 128
                                                      + (db + dsel) * 2));
                uint32_t vh[4], vl[4];
                ldmatrix_x4_t(vh[0], vh[1], vh[2], vh[3], VB + voff2);
                ldmatrix_x4_t(vl[0], vl[1], vl[2], vl[3], VB + 16384 + voff2);
                const int oj = db / 8;
                mma16816f(O[oj],     ph, vh[0], vh[1]);
                mma16816f(O[oj + 1], ph, vh[2], vh[3]);
                mma16816f(O[oj],     ph, vl[0], vl[1]);
                mma16816f(O[oj + 1], ph, vl[2], vl[3]);
            }
        }

        __syncthreads();
        if (kt + 1 < nb) {
            if (kt + 2 < nb) {
                flash_issue_kv(sb + 32768 + (kt & 1) * FL_STAGE, qh, ql,
                               (kt + 2) * 128, koff, voff, tid);
                cp_commit();
                cp_wait<1>();
            } else {
                cp_wait<0>();
            }
            __syncthreads();
        }
    }

    const float inv0 = 1.f / l_0, inv1 = 1.f / l_1;
    const int r0 = m0 + wm + (lane >> 2);
    const int col0 = h * 64 + 2 * (lane & 3);
#pragma unroll
    for (int nj = 0; nj < 8; ++nj) {
        const int col = col0 + nj * 8;
        __half2 o0 = __floats2half2_rn(O[nj][0] * inv0, O[nj][1] * inv0);
        __half2 o1 = __floats2half2_rn(O[nj][2] * inv1, O[nj][3] * inv1);
        *(uint32_t*)(y16 + (size_t)r0 * CDIM + col) =
            *reinterpret_cast<uint32_t*>(&o0);
        *(uint32_t*)(y16 + (size_t)(r0 + 8) * CDIM + col) =
            *reinterpret_cast<uint32_t*>(&o1);
    }
}

// ---------------------------------------------------------------------------
extern "C" void kernel_launch(void* const* d_in, const int* in_sizes, int n_in,
                              void* d_out, int out_size)
{
    const float* x      = (const float*)d_in[0];
    const float* cosb   = (const float*)d_in[1];
    const float* sinb   = (const float*)d_in[2];
    const float* W_attn = (const float*)d_in[3];
    const float* b_attn = (const float*)d_in[4];
    const float* W_proj = (const float*)d_in[5];
    const float* b_proj = (const float*)d_in[6];
    float* out = (float*)d_out;

    __half *qh, *ql, *x16, *wa, *wp, *y16;
    cudaGetSymbolAddress((void**)&qh,  g_qh);
    cudaGetSymbolAddress((void**)&ql,  g_ql);
    cudaGetSymbolAddress((void**)&x16, g_x16);
    cudaGetSymbolAddress((void**)&wa,  g_wa);
    cudaGetSymbolAddress((void**)&wp,  g_wp);
    cudaGetSymbolAddress((void**)&y16, g_y16);

    cudaFuncSetAttribute(gemm_f16<QKVD, CDIM, true>,
                         cudaFuncAttributeMaxDynamicSharedMemorySize, GEMM_SMEM_BYTES);
    cudaFuncSetAttribute(gemm_f16<CDIM, CDIM, false>,
                         cudaFuncAttributeMaxDynamicSharedMemorySize, GEMM_SMEM_BYTES);
    cudaFuncSetAttribute(flash_mma,
                         cudaFuncAttributeMaxDynamicSharedMemorySize, FLASH_SMEM_BYTES);

    // 0) converts: everything single-rounded fp16
    cvt_16<<<(TSEQ * CDIM / 2 + 255) / 256, 256>>>(x, x16, TSEQ * CDIM / 2);
    cvt_16<<<(QKVD * CDIM / 2 + 255) / 256, 256>>>(W_attn, wa, QKVD * CDIM / 2);
    cvt_16<<<(CDIM * CDIM / 2 + 255) / 256, 256>>>(W_proj, wp, CDIM * CDIM / 2);

    // 1) QKV GEMM + bias -> fp16 hi/lo qkv (single-product fp16)
    gemm_f16<QKVD, CDIM, true>
        <<<dim3(QKVD / 128, TSEQ / 128), 256, GEMM_SMEM_BYTES>>>(
            x16, wa, b_attn, nullptr, qh, ql);

    // 2) RoPE in place on fp16 hi/lo (scale folded into Q)
    rope_hl<<<TSEQ * 40 / 8, 256>>>(qh, ql, cosb, sinb);

    // 3) causal flash attention (fp16x2) -> fp16 y
    flash_mma<<<dim3(NHEAD, TSEQ / 128), 256, FLASH_SMEM_BYTES>>>(qh, ql, y16);

    // 4) output projection + bias -> fp32 out (single-product fp16)
    gemm_f16<CDIM, CDIM, false>
        <<<dim3(CDIM / 128, TSEQ / 128), 256, GEMM_SMEM_BYTES>>>(
            y16, wp, b_proj, out, nullptr, nullptr);
}

// round 17
// speedup vs baseline: 2.4904x; 1.2305x over previous
#include <cuda_runtime.h>
#include <cuda_bf16.h>
#include <cuda_fp16.h>
#include <math.h>
#include <stdint.h>

#define TSEQ 2048
#define CDIM 2048
#define QKVD 3072
#define NHEAD 32
#define HSZ 64

// scratch (no allocations allowed) — all single fp16
__device__ __half g_q16[TSEQ * QKVD];  // qkv
__device__ __half g_x16[TSEQ * CDIM];  // x
__device__ __half g_wa[QKVD * CDIM];   // W_attn
__device__ __half g_wp[CDIM * CDIM];   // W_proj
__device__ __half g_y16[TSEQ * CDIM];  // attn out

// ---------------------------------------------------------------------------
// helpers
// ---------------------------------------------------------------------------
__device__ __forceinline__ uint32_t smem_u32(const void* p) {
    uint32_t a;
    asm("{ .reg .u64 t; cvta.to.shared.u64 t, %1; cvt.u32.u64 %0, t; }"
        : "=r"(a) : "l"(p));
    return a;
}

__device__ __forceinline__ void ldmatrix_x4(uint32_t& r0, uint32_t& r1,
                                            uint32_t& r2, uint32_t& r3,
                                            uint32_t addr) {
    asm volatile("ldmatrix.sync.aligned.m8n8.x4.shared.b16 {%0,%1,%2,%3}, [%4];"
                 : "=r"(r0), "=r"(r1), "=r"(r2), "=r"(r3) : "r"(addr));
}

__device__ __forceinline__ void ldmatrix_x4_t(uint32_t& r0, uint32_t& r1,
                                              uint32_t& r2, uint32_t& r3,
                                              uint32_t addr) {
    asm volatile("ldmatrix.sync.aligned.m8n8.x4.trans.shared.b16 {%0,%1,%2,%3}, [%4];"
                 : "=r"(r0), "=r"(r1), "=r"(r2), "=r"(r3) : "r"(addr));
}

// fp16 mma
__device__ __forceinline__ void mma16816f(float* c, const uint32_t* a,
                                          uint32_t b0, uint32_t b1) {
    asm volatile(
        "mma.sync.aligned.m16n8k16.row.col.f32.f16.f16.f32 "
        "{%0,%1,%2,%3}, {%4,%5,%6,%7}, {%8,%9}, {%0,%1,%2,%3};"
        : "+f"(c[0]), "+f"(c[1]), "+f"(c[2]), "+f"(c[3])
        : "r"(a[0]), "r"(a[1]), "r"(a[2]), "r"(a[3]), "r"(b0), "r"(b1));
}

__device__ __forceinline__ void cp16(uint32_t dst, const void* src) {
    asm volatile("cp.async.cg.shared.global [%0], [%1], 16;"
                 :: "r"(dst), "l"(src) : "memory");
}
__device__ __forceinline__ void cp_commit() {
    asm volatile("cp.async.commit_group;" ::: "memory");
}
template<int N> __device__ __forceinline__ void cp_wait() {
    asm volatile("cp.async.wait_group %0;" :: "n"(N) : "memory");
}

#define SWZ(o)   ((o) ^ (((o) >> 3) & 0x70))

// ---------------------------------------------------------------------------
// converter: fp32 -> fp16 single
// ---------------------------------------------------------------------------
__global__ void __launch_bounds__(256)
cvt_16(const float* __restrict__ src, __half* __restrict__ w, int npairs)
{
    const int i = blockIdx.x * 256 + threadIdx.x;
    if (i >= npairs) return;
    float2 v = ((const float2*)src)[i];
    __half2 w2 = __floats2half2_rn(v.x, v.y);
    ((uint32_t*)w)[i] = *reinterpret_cast<uint32_t*>(&w2);
}

// ---------------------------------------------------------------------------
// fp16 single-product NT GEMM: C[M,N] = A[M,K]*B[N,K]^T + bias[N]
// 128x128 tile, BK=64, 256 threads (2x4 warps, warp tile 64x32),
// 3-stage cp.async pipeline (32KB/stage: A 16K, B 16K).
// OUT_F16: write single fp16 else fp32.
// ---------------------------------------------------------------------------
static constexpr int GSTAGE = 32768;
static constexpr int GEMM_SMEM_BYTES = 1024 + 3 * GSTAGE;   // 99328

__device__ __forceinline__ void gemm_issue(
    uint32_t stg, const __half* a0, const __half* b0, int KDIM, int tid)
{
    const __half* base[2] = {a0, b0};
#pragma unroll
    for (int t2 = 0; t2 < 2; ++t2) {
        const uint32_t tb = stg + t2 * 16384;
        const __half* src = base[t2];
#pragma unroll
        for (int it = 0; it < 4; ++it) {
            const int idx = it * 256 + tid;
            const int row = idx >> 3, ch = idx & 7;
            cp16(tb + SWZ((uint32_t)(row * 128 + ch * 16)),
                 src + (size_t)row * KDIM + ch * 8);
        }
    }
}

template<int NDIM, int KDIM, bool OUT_F16>
__global__ void __launch_bounds__(256, 1)
gemm_f16(const __half* __restrict__ A16, const __half* __restrict__ B16,
         const float* __restrict__ bias, float* __restrict__ C,
         __half* __restrict__ C16)
{
    extern __shared__ char smem_raw[];
    const uint32_t sb = (smem_u32(smem_raw) + 1023u) & ~1023u;

    const int tid  = threadIdx.x;
    const int wid  = tid >> 5;
    const int lane = tid & 31;
    const int m0 = blockIdx.y * 128;
    const int n0 = blockIdx.x * 128;
    const int wm = (wid >> 2) * 64;
    const int wn = (wid & 3) * 32;

    const __half* A0 = A16 + (size_t)m0 * KDIM;
    const __half* B0 = B16 + (size_t)n0 * KDIM;

    float acc[4][4][4];
#pragma unroll
    for (int i = 0; i < 4; ++i)
#pragma unroll
        for (int j = 0; j < 4; ++j)
#pragma unroll
            for (int r = 0; r < 4; ++r) acc[i][j][r] = 0.f;

    const int lrow16 = lane & 15;
    const int khalfB = (lane >> 4) * 16;
    const int ITERS = KDIM / 64;

    gemm_issue(sb,              A0,       B0,       KDIM, tid); cp_commit();
    gemm_issue(sb + GSTAGE,     A0 + 64,  B0 + 64,  KDIM, tid); cp_commit();
    gemm_issue(sb + 2 * GSTAGE, A0 + 128, B0 + 128, KDIM, tid); cp_commit();

    for (int kt = 0; kt < ITERS; ++kt) {
        const int sidx = kt % 3;
        const uint32_t stg = sb + sidx * GSTAGE;
        cp_wait<2>();
        __syncthreads();

#pragma unroll
        for (int s = 0; s < 4; ++s) {
            const uint32_t kb = (uint32_t)(s * 32 + khalfB);
            uint32_t bh[2][4];
#pragma unroll
            for (int nj2 = 0; nj2 < 2; ++nj2) {
                const uint32_t roff = SWZ((uint32_t)((wn + nj2 * 16 + lrow16) * 128) + kb);
                ldmatrix_x4(bh[nj2][0], bh[nj2][1], bh[nj2][2], bh[nj2][3],
                            stg + 16384 + roff);
            }
#pragma unroll
            for (int mi = 0; mi < 4; ++mi) {
                const uint32_t aoff = SWZ((uint32_t)((wm + mi * 16 + lrow16) * 128) + kb);
                uint32_t ah[4];
                ldmatrix_x4(ah[0], ah[1], ah[2], ah[3], stg + aoff);
#pragma unroll
                for (int nj = 0; nj < 4; ++nj)
                    mma16816f(acc[mi][nj], ah,
                              bh[nj >> 1][nj & 1], bh[nj >> 1][(nj & 1) + 2]);
            }
        }

        __syncthreads();
        if (kt + 3 < ITERS) {
            const int ko = (kt + 3) * 64;
            gemm_issue(stg, A0 + ko, B0 + ko, KDIM, tid);
        }
        cp_commit();
    }

    // epilogue
    const int qrow = lane >> 2;
    const int qcol = (lane & 3) * 2;
#pragma unroll
    for (int mi = 0; mi < 4; ++mi) {
        const int r0 = m0 + wm + mi * 16 + qrow;
#pragma unroll
        for (int nj = 0; nj < 4; ++nj) {
            const int c0 = n0 + wn + nj * 8 + qcol;
            const float bx = bias[c0], by = bias[c0 + 1];
            const float v00 = acc[mi][nj][0] + bx, v01 = acc[mi][nj][1] + by;
            const float v10 = acc[mi][nj][2] + bx, v11 = acc[mi][nj][3] + by;
            if (OUT_F16) {
                __half2 h0 = __floats2half2_rn(v00, v01);
                __half2 h1 = __floats2half2_rn(v10, v11);
                *(uint32_t*)(C16 + (size_t)r0 * NDIM + c0) =
                    *reinterpret_cast<uint32_t*>(&h0);
                *(uint32_t*)(C16 + (size_t)(r0 + 8) * NDIM + c0) =
                    *reinterpret_cast<uint32_t*>(&h1);
            } else {
                *(float2*)&C[(size_t)r0 * NDIM + c0]       = make_float2(v00, v01);
                *(float2*)&C[(size_t)(r0 + 8) * NDIM + c0] = make_float2(v10, v11);
            }
        }
    }
}

// ---------------------------------------------------------------------------
// RoPE in-place on qkv (single fp16). One warp per (token, rope-slot).
// ---------------------------------------------------------------------------
__global__ void __launch_bounds__(256)
rope_f16(__half* __restrict__ q16,
         const float* __restrict__ cosb, const float* __restrict__ sinb)
{
    const int gid  = blockIdx.x * 8 + (threadIdx.x >> 5);
    const int lane = threadIdx.x & 31;
    const int t   = gid / 40;
    const int s40 = gid % 40;
    const int ss  = s40 % 5;             // 0-3 q, 4 k
    const int slot = (s40 / 5) * 6 + ss;
    const int d = 2 * lane;

    const size_t off = (size_t)t * QKVD + slot * 64 + d;
    uint32_t u = *(const uint32_t*)(q16 + off);
    __half2 hv = *reinterpret_cast<__half2*>(&u);
    float2 v = __half22float2(hv);

    float px = __shfl_xor_sync(0xffffffffu, v.x, 4);
    float py = __shfl_xor_sync(0xffffffffu, v.y, 4);
    if (d < 16) {
        const float rx = (d < 8) ? -px : px;
        const float ry = (d < 8) ? -py : py;
        const float c0 = cosb[t * 16 + d],     s0 = sinb[t * 16 + d];
        const float c1 = cosb[t * 16 + d + 1], s1 = sinb[t * 16 + d + 1];
        v.x = v.x * c0 + rx * s0;
        v.y = v.y * c1 + ry * s1;
    }
    if (ss < 4) { v.x *= 0.125f; v.y *= 0.125f; }

    __half2 hw = __floats2half2_rn(v.x, v.y);
    *(uint32_t*)(q16 + off) = *reinterpret_cast<uint32_t*>(&hw);
}

// ---------------------------------------------------------------------------
// Flash attention, causal, single-product fp16: S = Q*K, O = P*V.
// KV stage: [K 16K][V 16K] = 32KB, double-buffered. Q 16KB resident.
// ---------------------------------------------------------------------------
static constexpr int FL_STAGE = 32768;
static constexpr int FLASH_SMEM_BYTES = 1024 + 16384 + 2 * FL_STAGE;   // 82944

__device__ __forceinline__ void flash_issue_kv(
    uint32_t SB, const __half* q16, int n0, int koff, int voff, int tid)
{
#pragma unroll
    for (int p = 0; p < 4; ++p) {
        const int idx = p * 256 + tid;
        const int row = idx >> 3, ch = idx & 7;
        const uint32_t off = SWZ((uint32_t)(row * 128 + ch * 16));
        const size_t gk = (size_t)(n0 + row) * QKVD + koff + ch * 8;
        const size_t gv = (size_t)(n0 + row) * QKVD + voff + ch * 8;
        cp16(SB + off,         q16 + gk);
        cp16(SB + 16384 + off, q16 + gv);
    }
}

__global__ void __launch_bounds__(256, 1)
flash_mma(const __half* __restrict__ q16, __half* __restrict__ y16)
{
    extern __shared__ char smem_raw[];
    const uint32_t sb = (smem_u32(smem_raw) + 1023u) & ~1023u;

    const int tid  = threadIdx.x;
    const int wid  = tid >> 5;
    const int lane = tid & 31;
    const int h  = blockIdx.x;
    const int m0 = (15 - (int)blockIdx.y) * 128;
    const int nb = m0 / 128 + 1;
    const int g = h >> 2;
    const int qoff = g * 384 + (h & 3) * 64;
    const int koff = g * 384 + 256;
    const int voff = g * 384 + 320;
    const int wm = wid * 16;

    // Q tile (single fp16, 16KB)
#pragma unroll
    for (int p = 0; p < 2; ++p) {
        const int idx = p * 256 + tid;
        const int row = idx >> 2, ch = idx & 3;       // 128 rows x 4 chunks... wait
        (void)row; (void)ch;
    }
    // 128 rows x 128B = 1024 chunks of 16B -> 4 iters of 256 threads
#pragma unroll
    for (int p = 0; p < 4; ++p) {
        const int idx = p * 256 + tid;
        const int row = idx >> 3, ch = idx & 7;
        const uint32_t off = SWZ((uint32_t)(row * 128 + ch * 16));
        const size_t gq = (size_t)(m0 + row) * QKVD + qoff + ch * 8;
        cp16(sb + off, q16 + gq);
    }
    flash_issue_kv(sb + 16384, q16, 0, koff, voff, tid);
    cp_commit();
    if (nb > 1) {
        flash_issue_kv(sb + 16384 + FL_STAGE, q16, 128, koff, voff, tid);
        cp_commit();
        cp_wait<1>();
    } else {
        cp_wait<0>();
    }
    __syncthreads();

    uint32_t qf[4][4];
#pragma unroll
    for (int s = 0; s < 4; ++s) {
        const uint32_t aoff = SWZ((uint32_t)((wm + (lane & 15)) * 128
                                             + s * 32 + (lane >> 4) * 16));
        ldmatrix_x4(qf[s][0], qf[s][1], qf[s][2], qf[s][3], sb + aoff);
    }

    float O[8][4];
#pragma unroll
    for (int nj = 0; nj < 8; ++nj)
#pragma unroll
        for (int r = 0; r < 4; ++r) O[nj][r] = 0.f;
    float m_0 = -1e30f, m_1 = -1e30f, l_0 = 0.f, l_1 = 0.f;

    for (int kt = 0; kt < nb; ++kt) {
        const uint32_t SB = sb + 16384 + (kt & 1) * FL_STAGE;
        const uint32_t VB = SB + 16384;

        float S[16][4];
#pragma unroll
        for (int nf = 0; nf < 16; ++nf)
#pragma unroll
            for (int r = 0; r < 4; ++r) S[nf][r] = 0.f;

#pragma unroll
        for (int s = 0; s < 4; ++s) {
            const uint32_t kb = (uint32_t)(s * 32 + (lane >> 4) * 16);
#pragma unroll
            for (int njp = 0; njp < 8; ++njp) {
                const uint32_t roff = SWZ((uint32_t)((njp * 16 + (lane & 15)) * 128) + kb);
                uint32_t kh[4];
                ldmatrix_x4(kh[0], kh[1], kh[2], kh[3], SB + roff);
                mma16816f(S[2 * njp],     qf[s], kh[0], kh[2]);
                mma16816f(S[2 * njp + 1], qf[s], kh[1], kh[3]);
            }
        }

        if (kt == nb - 1) {
            const int bc = 2 * (lane & 3);
            const int lim0 = wm + (lane >> 2);
            const int lim1 = lim0 + 8;
#pragma unroll
            for (int nf = 0; nf < 16; ++nf) {
                const int c0 = nf * 8 + bc;
                if (c0 > lim0)     S[nf][0] = -1e30f;
                if (c0 + 1 > lim0) S[nf][1] = -1e30f;
                if (c0 > lim1)     S[nf][2] = -1e30f;
                if (c0 + 1 > lim1) S[nf][3] = -1e30f;
            }
        }

        float mx0 = -1e30f, mx1 = -1e30f;
#pragma unroll
        for (int nf = 0; nf < 16; ++nf) {
            mx0 = fmaxf(mx0, fmaxf(S[nf][0], S[nf][1]));
            mx1 = fmaxf(mx1, fmaxf(S[nf][2], S[nf][3]));
        }
        mx0 = fmaxf(mx0, __shfl_xor_sync(0xffffffffu, mx0, 1));
        mx0 = fmaxf(mx0, __shfl_xor_sync(0xffffffffu, mx0, 2));
        mx1 = fmaxf(mx1, __shfl_xor_sync(0xffffffffu, mx1, 1));
        mx1 = fmaxf(mx1, __shfl_xor_sync(0xffffffffu, mx1, 2));
        const float mn0 = fmaxf(m_0, mx0), mn1 = fmaxf(m_1, mx1);
        const float f0 = __expf(m_0 - mn0), f1 = __expf(m_1 - mn1);
        m_0 = mn0; m_1 = mn1;

        float rs0 = 0.f, rs1 = 0.f;
#pragma unroll
        for (int nf = 0; nf < 16; ++nf) {
            S[nf][0] = __expf(S[nf][0] - mn0);
            S[nf][1] = __expf(S[nf][1] - mn0);
            S[nf][2] = __expf(S[nf][2] - mn1);
            S[nf][3] = __expf(S[nf][3] - mn1);
            rs0 += S[nf][0] + S[nf][1];
            rs1 += S[nf][2] + S[nf][3];
        }
        rs0 += __shfl_xor_sync(0xffffffffu, rs0, 1);
        rs0 += __shfl_xor_sync(0xffffffffu, rs0, 2);
        rs1 += __shfl_xor_sync(0xffffffffu, rs1, 1);
        rs1 += __shfl_xor_sync(0xffffffffu, rs1, 2);
        l_0 = l_0 * f0 + rs0;
        l_1 = l_1 * f1 + rs1;
#pragma unroll
        for (int nj = 0; nj < 8; ++nj) {
            O[nj][0] *= f0; O[nj][1] *= f0;
            O[nj][2] *= f1; O[nj][3] *= f1;
        }

        const uint32_t kr   = (uint32_t)(((lane & 8) ? 8 : 0) + (lane & 7));
        const uint32_t dsel = (lane & 16) ? 8u : 0u;
#pragma unroll
        for (int t = 0; t < 8; ++t) {
            uint32_t ph[4];
            {
                __half2 p0 = __floats2half2_rn(S[2 * t][0],     S[2 * t][1]);
                __half2 p1 = __floats2half2_rn(S[2 * t][2],     S[2 * t][3]);
                __half2 p2 = __floats2half2_rn(S[2 * t + 1][0], S[2 * t + 1][1]);
                __half2 p3 = __floats2half2_rn(S[2 * t + 1][2], S[2 * t + 1][3]);
                ph[0] = *reinterpret_cast<uint32_t*>(&p0);
                ph[1] = *reinterpret_cast<uint32_t*>(&p1);
                ph[2] = *reinterpret_cast<uint32_t*>(&p2);
                ph[3] = *reinterpret_cast<uint32_t*>(&p3);
            }
#pragma unroll
            for (int db = 0; db < 64; db += 16) {
                const uint32_t voff2 = SWZ((uint32_t)((t * 16 + kr) * 128
                                                      + (db + dsel) * 2));
                uint32_t vh[4];
                ldmatrix_x4_t(vh[0], vh[1], vh[2], vh[3], VB + voff2);
                const int oj = db / 8;
                mma16816f(O[oj],     ph, vh[0], vh[1]);
                mma16816f(O[oj + 1], ph, vh[2], vh[3]);
            }
        }

        __syncthreads();
        if (kt + 1 < nb) {
            if (kt + 2 < nb) {
                flash_issue_kv(sb + 16384 + (kt & 1) * FL_STAGE, q16,
                               (kt + 2) * 128, koff, voff, tid);
                cp_commit();
                cp_wait<1>();
            } else {
                cp_wait<0>();
            }
            __syncthreads();
        }
    }

    const float inv0 = 1.f / l_0, inv1 = 1.f / l_1;
    const int r0 = m0 + wm + (lane >> 2);
    const int col0 = h * 64 + 2 * (lane & 3);
#pragma unroll
    for (int nj = 0; nj < 8; ++nj) {
        const int col = col0 + nj * 8;
        __half2 o0 = __floats2half2_rn(O[nj][0] * inv0, O[nj][1] * inv0);
        __half2 o1 = __floats2half2_rn(O[nj][2] * inv1, O[nj][3] * inv1);
        *(uint32_t*)(y16 + (size_t)r0 * CDIM + col) =
            *reinterpret_cast<uint32_t*>(&o0);
        *(uint32_t*)(y16 + (size_t)(r0 + 8) * CDIM + col) =
            *reinterpret_cast<uint32_t*>(&o1);
    }
}

// ---------------------------------------------------------------------------
extern "C" void kernel_launch(void* const* d_in, const int* in_sizes, int n_in,
                              void* d_out, int out_size)
{
    const float* x      = (const float*)d_in[0];
    const float* cosb   = (const float*)d_in[1];
    const float* sinb   = (const float*)d_in[2];
    const float* W_attn = (const float*)d_in[3];
    const float* b_attn = (const float*)d_in[4];
    const float* W_proj = (const float*)d_in[5];
    const float* b_proj = (const float*)d_in[6];
    float* out = (float*)d_out;

    __half *q16, *x16, *wa, *wp, *y16;
    cudaGetSymbolAddress((void**)&q16, g_q16);
    cudaGetSymbolAddress((void**)&x16, g_x16);
    cudaGetSymbolAddress((void**)&wa,  g_wa);
    cudaGetSymbolAddress((void**)&wp,  g_wp);
    cudaGetSymbolAddress((void**)&y16, g_y16);

    cudaFuncSetAttribute(gemm_f16<QKVD, CDIM, true>,
                         cudaFuncAttributeMaxDynamicSharedMemorySize, GEMM_SMEM_BYTES);
    cudaFuncSetAttribute(gemm_f16<CDIM, CDIM, false>,
                         cudaFuncAttributeMaxDynamicSharedMemorySize, GEMM_SMEM_BYTES);
    cudaFuncSetAttribute(flash_mma,
                         cudaFuncAttributeMaxDynamicSharedMemorySize, FLASH_SMEM_BYTES);

    // 0) converts to fp16
    cvt_16<<<(TSEQ * CDIM / 2 + 255) / 256, 256>>>(x, x16, TSEQ * CDIM / 2);
    cvt_16<<<(QKVD * CDIM / 2 + 255) / 256, 256>>>(W_attn, wa, QKVD * CDIM / 2);
    cvt_16<<<(CDIM * CDIM / 2 + 255) / 256, 256>>>(W_proj, wp, CDIM * CDIM / 2);

    // 1) QKV GEMM + bias -> fp16 qkv
    gemm_f16<QKVD, CDIM, true>
        <<<dim3(QKVD / 128, TSEQ / 128), 256, GEMM_SMEM_BYTES>>>(
            x16, wa, b_attn, nullptr, q16);

    // 2) RoPE in place (scale folded into Q)
    rope_f16<<<TSEQ * 40 / 8, 256>>>(q16, cosb, sinb);

    // 3) causal flash attention (single-product fp16) -> fp16 y
    flash_mma<<<dim3(NHEAD, TSEQ / 128), 256, FLASH_SMEM_BYTES>>>(q16, y16);

    // 4) output projection + bias -> fp32 out
    gemm_f16<CDIM, CDIM, false>
        <<<dim3(CDIM / 128, TSEQ / 128), 256, GEMM_SMEM_BYTES>>>(
            y16, wp, b_proj, out, nullptr);
}